// round 7
// baseline (speedup 1.0000x reference)
#include <cuda_runtime.h>
#include <math.h>

// Problem constants
#define BB 4
#define SS 1024
#define DD 1024
#define HH 16
#define DHH 64
#define DFF 4096
#define NLAYERS 4
#define MM (BB*SS)          // 4096 rows

// ---------------------------------------------------------------------------
// Scratch (static device globals -- no allocation allowed)
// ---------------------------------------------------------------------------
__device__ float g_x  [(size_t)MM * DD];        // 16 MB  current activations
__device__ float g_qkv[(size_t)MM * 3 * DD];    // 48 MB
__device__ float g_o  [(size_t)MM * DD];        // 16 MB  attention output
__device__ float g_h  [(size_t)MM * DFF];       // 64 MB  FF hidden
__device__ float g_tmp[(size_t)MM * DD];        // 16 MB  pre-LN buffer

// ---------------------------------------------------------------------------
// NT SGEMM: C[M,N] = A[M,K] @ B[N,K]^T (+bias, +relu / +residual)
// 128x128 tile, BK=16, 256 threads, 8x8 microtile. M,N,K all % 128 == 0.
// ---------------------------------------------------------------------------
enum { EPI_BIAS = 0, EPI_RELU = 1, EPI_RES = 2 };

template<int EPI>
__global__ __launch_bounds__(256, 2)
void gemm_nt(const float* __restrict__ A, const float* __restrict__ Bm,
             const float* __restrict__ bias, const float* __restrict__ Res,
             float* __restrict__ C, int K, int N)
{
    __shared__ float As[16][132];
    __shared__ float Bs[16][132];

    const int tid = threadIdx.x;
    const int m0 = blockIdx.y << 7;
    const int n0 = blockIdx.x << 7;
    const int tx = tid & 15;            // 0..15  -> N microtile
    const int ty = tid >> 4;            // 0..15  -> M microtile
    const int r0 = tid >> 2;            // 0..63  load row
    const int cg = (tid & 3) << 2;      // 0,4,8,12 load col group

    const float* Ap = A  + (size_t)(m0 + r0) * K + cg;
    const float* Bp = Bm + (size_t)(n0 + r0) * K + cg;
    const size_t half = (size_t)64 * K;

    float acc[8][8];
#pragma unroll
    for (int i = 0; i < 8; i++)
#pragma unroll
        for (int j = 0; j < 8; j++) acc[i][j] = 0.f;

    for (int k0 = 0; k0 < K; k0 += 16) {
        float4 a0 = *(const float4*)(Ap + k0);
        float4 a1 = *(const float4*)(Ap + half + k0);
        float4 b0 = *(const float4*)(Bp + k0);
        float4 b1 = *(const float4*)(Bp + half + k0);
        __syncthreads();   // previous compute done before overwriting smem
        As[cg+0][r0]    = a0.x; As[cg+1][r0]    = a0.y; As[cg+2][r0]    = a0.z; As[cg+3][r0]    = a0.w;
        As[cg+0][r0+64] = a1.x; As[cg+1][r0+64] = a1.y; As[cg+2][r0+64] = a1.z; As[cg+3][r0+64] = a1.w;
        Bs[cg+0][r0]    = b0.x; Bs[cg+1][r0]    = b0.y; Bs[cg+2][r0]    = b0.z; Bs[cg+3][r0]    = b0.w;
        Bs[cg+0][r0+64] = b1.x; Bs[cg+1][r0+64] = b1.y; Bs[cg+2][r0+64] = b1.z; Bs[cg+3][r0+64] = b1.w;
        __syncthreads();

#pragma unroll
        for (int kk = 0; kk < 16; kk++) {
            float a[8], b[8];
            *(float4*)(a)     = *(const float4*)&As[kk][ty << 3];
            *(float4*)(a + 4) = *(const float4*)&As[kk][(ty << 3) + 4];
            *(float4*)(b)     = *(const float4*)&Bs[kk][tx << 3];
            *(float4*)(b + 4) = *(const float4*)&Bs[kk][(tx << 3) + 4];
#pragma unroll
            for (int i = 0; i < 8; i++)
#pragma unroll
                for (int j = 0; j < 8; j++)
                    acc[i][j] += a[i] * b[j];
        }
    }

    float bv[8];
#pragma unroll
    for (int j = 0; j < 8; j++) bv[j] = bias[n0 + (tx << 3) + j];

#pragma unroll
    for (int i = 0; i < 8; i++) {
        const int m = m0 + (ty << 3) + i;
        const size_t off = (size_t)m * N + n0 + (tx << 3);
        float v[8];
#pragma unroll
        for (int j = 0; j < 8; j++) {
            float t = acc[i][j] + bv[j];
            if (EPI == EPI_RELU) t = fmaxf(t, 0.f);
            v[j] = t;
        }
        if (EPI == EPI_RES) {
            float4 ra = *(const float4*)(Res + off);
            float4 rb = *(const float4*)(Res + off + 4);
            v[0] += ra.x; v[1] += ra.y; v[2] += ra.z; v[3] += ra.w;
            v[4] += rb.x; v[5] += rb.y; v[6] += rb.z; v[7] += rb.w;
        }
        *(float4*)(C + off)     = make_float4(v[0], v[1], v[2], v[3]);
        *(float4*)(C + off + 4) = make_float4(v[4], v[5], v[6], v[7]);
    }
}

// ---------------------------------------------------------------------------
// Block-causal flash attention. BLK=64 == tile size -> no intra-tile masking.
// grid = (S/64, B*H), 256 threads = 8 warps. Warp w owns query rows 8w..8w+7.
// Lane owns 2 key-columns (scores) / 2 headdim-columns (output).
// smem: Q[64][68], K/P[64][68], V[64][68]  (52224 B dynamic)
// ---------------------------------------------------------------------------
#define AST 68
#define ATTN_SMEM (3 * 64 * AST * 4)

__global__ __launch_bounds__(256)
void attn_kernel(const float* __restrict__ qkv, float* __restrict__ o)
{
    extern __shared__ float sm[];
    float* Qs = sm;                  // 64 x 68
    float* Ks = sm + 64 * AST;       // 64 x 68, reused as P
    float* Vs = sm + 2 * 64 * AST;   // 64 x 68

    const int jq   = blockIdx.x;
    const int b    = blockIdx.y >> 4;
    const int h    = blockIdx.y & 15;
    const int tid  = threadIdx.x;
    const int lane = tid & 31;
    const int warp = tid >> 5;
    const int r0   = warp << 3;

    const float* qbase = qkv + ((size_t)b * SS + (size_t)jq * 64) * 3072 + h * 64;
    const float* kbase = qkv + (size_t)b * SS * 3072 + 1024 + h * 64;
    const float* vbase = kbase + 1024;

    // Load Q tile (fold softmax scale 1/sqrt(64) = 0.125)
    for (int f = tid; f < 1024; f += 256) {
        int r = f >> 4, c4 = (f & 15) << 2;
        float4 v = *(const float4*)(qbase + (size_t)r * 3072 + c4);
        float* q = &Qs[r * AST + c4];
        q[0] = v.x * 0.125f; q[1] = v.y * 0.125f; q[2] = v.z * 0.125f; q[3] = v.w * 0.125f;
    }

    float O0[8], O1[8], mr[8], lr[8];
#pragma unroll
    for (int i = 0; i < 8; i++) { O0[i] = 0.f; O1[i] = 0.f; mr[i] = -INFINITY; lr[i] = 0.f; }

    for (int kb = 0; kb <= jq; kb++) {
        __syncthreads();   // prior AV done (and Q ready on first iter)
        for (int f = tid; f < 1024; f += 256) {
            int r = f >> 4, c4 = (f & 15) << 2;
            size_t roff = (size_t)(kb * 64 + r) * 3072 + c4;
            float4 kv = *(const float4*)(kbase + roff);
            float4 vv = *(const float4*)(vbase + roff);
            float* kp = &Ks[r * AST + c4];
            float* vp = &Vs[r * AST + c4];
            kp[0] = kv.x; kp[1] = kv.y; kp[2] = kv.z; kp[3] = kv.w;
            vp[0] = vv.x; vp[1] = vv.y; vp[2] = vv.z; vp[3] = vv.w;
        }
        __syncthreads();

        // S = Q K^T : each lane -> 8 rows x 2 key cols
        float sc0[8], sc1[8];
#pragma unroll
        for (int i = 0; i < 8; i++) { sc0[i] = 0.f; sc1[i] = 0.f; }
        const float* kr0 = &Ks[(2 * lane) * AST];
        const float* kr1 = kr0 + AST;
#pragma unroll
        for (int d4 = 0; d4 < 64; d4 += 4) {
            float4 k0 = *(const float4*)(kr0 + d4);
            float4 k1 = *(const float4*)(kr1 + d4);
#pragma unroll
            for (int i = 0; i < 8; i++) {
                float4 q = *(const float4*)&Qs[(r0 + i) * AST + d4];
                sc0[i] += q.x * k0.x + q.y * k0.y + q.z * k0.z + q.w * k0.w;
                sc1[i] += q.x * k1.x + q.y * k1.y + q.z * k1.z + q.w * k1.w;
            }
        }
        __syncthreads();   // all warps done reading K -> safe to overwrite with P

        // online softmax, write P into Ks (warp-private rows)
#pragma unroll
        for (int i = 0; i < 8; i++) {
            float mb = fmaxf(sc0[i], sc1[i]);
#pragma unroll
            for (int off = 16; off; off >>= 1) mb = fmaxf(mb, __shfl_xor_sync(0xffffffffu, mb, off));
            float mnew  = fmaxf(mr[i], mb);
            float alpha = __expf(mr[i] - mnew);
            float p0 = __expf(sc0[i] - mnew);
            float p1 = __expf(sc1[i] - mnew);
            float s  = p0 + p1;
#pragma unroll
            for (int off = 16; off; off >>= 1) s += __shfl_xor_sync(0xffffffffu, s, off);
            lr[i] = lr[i] * alpha + s;
            mr[i] = mnew;
            O0[i] *= alpha; O1[i] *= alpha;
            Ks[(r0 + i) * AST + 2 * lane]     = p0;
            Ks[(r0 + i) * AST + 2 * lane + 1] = p1;
        }
        __syncwarp();

        // O += P @ V : lane -> 8 rows x 2 headdim cols
#pragma unroll 4
        for (int kc = 0; kc < 64; kc++) {
            float2 v = *(const float2*)&Vs[kc * AST + 2 * lane];
#pragma unroll
            for (int i = 0; i < 8; i++) {
                float p = Ks[(r0 + i) * AST + kc];
                O0[i] += p * v.x;
                O1[i] += p * v.y;
            }
        }
    }

    float* obase = o + ((size_t)b * SS + (size_t)jq * 64) * DD + h * 64;
#pragma unroll
    for (int i = 0; i < 8; i++) {
        float inv = 1.0f / lr[i];
        *(float2*)(obase + (size_t)(r0 + i) * DD + 2 * lane) =
            make_float2(O0[i] * inv, O1[i] * inv);
    }
}

// ---------------------------------------------------------------------------
// LayerNorm over D=1024, one block (256 threads) per row
// ---------------------------------------------------------------------------
__global__ __launch_bounds__(256)
void ln_kernel(const float* __restrict__ in, const float* __restrict__ w,
               const float* __restrict__ b, float* __restrict__ out)
{
    __shared__ float s_sum[8], s_sq[8], s_bc[2];
    const int row = blockIdx.x, tid = threadIdx.x;
    float4 v = ((const float4*)(in + (size_t)row * 1024))[tid];
    float s = v.x + v.y + v.z + v.w;
    float q = v.x * v.x + v.y * v.y + v.z * v.z + v.w * v.w;
#pragma unroll
    for (int o = 16; o; o >>= 1) {
        s += __shfl_xor_sync(0xffffffffu, s, o);
        q += __shfl_xor_sync(0xffffffffu, q, o);
    }
    if ((tid & 31) == 0) { s_sum[tid >> 5] = s; s_sq[tid >> 5] = q; }
    __syncthreads();
    if (tid == 0) {
        float ts = 0.f, tq = 0.f;
#pragma unroll
        for (int i = 0; i < 8; i++) { ts += s_sum[i]; tq += s_sq[i]; }
        float mu  = ts * (1.f / 1024.f);
        float var = tq * (1.f / 1024.f) - mu * mu;
        s_bc[0] = mu;
        s_bc[1] = rsqrtf(var + 1e-5f);
    }
    __syncthreads();
    float mu = s_bc[0], rs = s_bc[1];
    float4 wv = ((const float4*)w)[tid];
    float4 bv = ((const float4*)b)[tid];
    float4 ov;
    ov.x = (v.x - mu) * rs * wv.x + bv.x;
    ov.y = (v.y - mu) * rs * wv.y + bv.y;
    ov.z = (v.z - mu) * rs * wv.z + bv.z;
    ov.w = (v.w - mu) * rs * wv.w + bv.w;
    ((float4*)(out + (size_t)row * 1024))[tid] = ov;
}

__global__ void copy_kernel(const float4* __restrict__ s, float4* __restrict__ d)
{
    int i = blockIdx.x * 256 + threadIdx.x;
    d[i] = s[i];
}

// ---------------------------------------------------------------------------
// Host orchestration (graph-capturable: kernel launches only)
// ---------------------------------------------------------------------------
extern "C" void kernel_launch(void* const* d_in, const int* in_sizes, int n_in,
                              void* d_out, int out_size)
{
    (void)in_sizes; (void)n_in; (void)out_size;
    const float* x_in = (const float*)d_in[0];
    const float* ipw  = (const float*)d_in[1];   // [L,3072,1024]
    const float* ipb  = (const float*)d_in[2];   // [L,3072]
    const float* ow   = (const float*)d_in[3];   // [L,1024,1024]
    const float* ob   = (const float*)d_in[4];   // [L,1024]
    const float* n1w  = (const float*)d_in[5];   // ln1
    const float* n1b  = (const float*)d_in[6];
    const float* f1w  = (const float*)d_in[7];   // [L,4096,1024]
    const float* f1b  = (const float*)d_in[8];   // [L,4096]
    const float* f2w  = (const float*)d_in[9];   // [L,1024,4096]
    const float* f2b  = (const float*)d_in[10];  // [L,1024]
    const float* n2w  = (const float*)d_in[11];  // ln2
    const float* n2b  = (const float*)d_in[12];
    float* out = (float*)d_out;

    float *px, *pqkv, *po, *ph, *ptmp;
    cudaGetSymbolAddress((void**)&px,   g_x);
    cudaGetSymbolAddress((void**)&pqkv, g_qkv);
    cudaGetSymbolAddress((void**)&po,   g_o);
    cudaGetSymbolAddress((void**)&ph,   g_h);
    cudaGetSymbolAddress((void**)&ptmp, g_tmp);

    cudaFuncSetAttribute((const void*)attn_kernel,
                         cudaFuncAttributeMaxDynamicSharedMemorySize, ATTN_SMEM);

    // x -> working buffer (4M floats = 1M float4)
    copy_kernel<<<4096, 256>>>((const float4*)x_in, (float4*)px);

    for (int l = 0; l < NLAYERS; l++) {
        const float* Wqkv = ipw + (size_t)l * 3 * DD * DD;
        const float* Bqkv = ipb + (size_t)l * 3 * DD;
        const float* Wout = ow  + (size_t)l * DD * DD;
        const float* Bout = ob  + (size_t)l * DD;
        const float* W1   = f1w + (size_t)l * DFF * DD;
        const float* B1   = f1b + (size_t)l * DFF;
        const float* W2   = f2w + (size_t)l * DD * DFF;
        const float* B2   = f2b + (size_t)l * DD;

        // qkv = x @ Wqkv^T + b
        gemm_nt<EPI_BIAS><<<dim3(24, 32), 256>>>(px, Wqkv, Bqkv, nullptr, pqkv, DD, 3 * DD);
        // block-causal attention
        attn_kernel<<<dim3(SS / 64, BB * HH), 256, ATTN_SMEM>>>(pqkv, po);
        // tmp = x + o @ Wout^T + b
        gemm_nt<EPI_RES><<<dim3(8, 32), 256>>>(po, Wout, Bout, px, ptmp, DD, DD);
        // x = LN1(tmp)
        ln_kernel<<<MM, 256>>>(ptmp, n1w + (size_t)l * DD, n1b + (size_t)l * DD, px);
        // h = relu(x @ W1^T + b1)
        gemm_nt<EPI_RELU><<<dim3(32, 32), 256>>>(px, W1, B1, nullptr, ph, DD, DFF);
        // tmp = x + h @ W2^T + b2
        gemm_nt<EPI_RES><<<dim3(8, 32), 256>>>(ph, W2, B2, px, ptmp, DFF, DD);
        // x = LN2(tmp)  (last layer writes final output)
        ln_kernel<<<MM, 256>>>(ptmp, n2w + (size_t)l * DD, n2b + (size_t)l * DD,
                               (l == NLAYERS - 1) ? out : px);
    }
}

// round 10
// speedup vs baseline: 1.9340x; 1.9340x over previous
#include <cuda_runtime.h>
#include <cuda_bf16.h>
#include <math.h>
#include <stdint.h>

// Problem constants
#define BB 4
#define SS 1024
#define DD 1024
#define HH 16
#define DFF 4096
#define NLAYERS 4
#define MM (BB*SS)          // 4096 rows

// ---------------------------------------------------------------------------
// Scratch (static device globals -- no allocation allowed)
// ---------------------------------------------------------------------------
__device__ float g_x  [(size_t)MM * DD];        // activations
__device__ float g_qkv[(size_t)MM * 3 * DD];
__device__ float g_o  [(size_t)MM * DD];
__device__ float g_h  [(size_t)MM * DFF];
__device__ float g_tmp[(size_t)MM * DD];
// split-bf16 operand buffers (reused per GEMM, graph executes sequentially)
__device__ __nv_bfloat16 g_ah[(size_t)MM * DFF];          // A hi (max 16M elems)
__device__ __nv_bfloat16 g_al[(size_t)MM * DFF];          // A lo
__device__ __nv_bfloat16 g_wh[(size_t)4 * 1024 * 1024];   // W hi (max 4M elems)
__device__ __nv_bfloat16 g_wl[(size_t)4 * 1024 * 1024];   // W lo

// ---------------------------------------------------------------------------
// Helpers
// ---------------------------------------------------------------------------
__device__ __forceinline__ uint32_t smem_u32(const void* p) {
    uint32_t a;
    asm("{ .reg .u64 t; cvta.to.shared.u64 t, %1; cvt.u32.u64 %0, t; }"
        : "=r"(a) : "l"(p));
    return a;
}
__device__ __forceinline__ uint32_t swz(uint32_t off) {
    return off ^ ((off >> 3) & 0x70);
}

#define CP_ASYNC16(dst, src) \
    asm volatile("cp.async.cg.shared.global [%0], [%1], 16;" :: "r"(dst), "l"(src))
#define CP_COMMIT() asm volatile("cp.async.commit_group;")
#define CP_WAIT1()  asm volatile("cp.async.wait_group 1;")

__device__ __forceinline__ void ldsm4(uint32_t* r, uint32_t addr) {
    asm volatile("ldmatrix.sync.aligned.m8n8.x4.shared.b16 {%0,%1,%2,%3}, [%4];"
        : "=r"(r[0]), "=r"(r[1]), "=r"(r[2]), "=r"(r[3]) : "r"(addr));
}
__device__ __forceinline__ void mma16816(float* d, const uint32_t* a, const uint32_t* b) {
    asm volatile(
        "mma.sync.aligned.m16n8k16.row.col.f32.bf16.bf16.f32 "
        "{%0,%1,%2,%3}, {%4,%5,%6,%7}, {%8,%9}, {%0,%1,%2,%3};"
        : "+f"(d[0]), "+f"(d[1]), "+f"(d[2]), "+f"(d[3])
        : "r"(a[0]), "r"(a[1]), "r"(a[2]), "r"(a[3]), "r"(b[0]), "r"(b[1]));
}

// ---------------------------------------------------------------------------
// fp32 -> (hi, lo) bf16 split (elementwise, memory-bound)
// ---------------------------------------------------------------------------
__global__ __launch_bounds__(256)
void split_kernel(const float4* __restrict__ in, uint2* __restrict__ hi,
                  uint2* __restrict__ lo, int n4)
{
    int i = blockIdx.x * 256 + threadIdx.x;
    if (i >= n4) return;
    float4 v = in[i];
    __nv_bfloat162 h0 = __floats2bfloat162_rn(v.x, v.y);
    __nv_bfloat162 h1 = __floats2bfloat162_rn(v.z, v.w);
    __nv_bfloat162 l0 = __floats2bfloat162_rn(v.x - __low2float(h0), v.y - __high2float(h0));
    __nv_bfloat162 l1 = __floats2bfloat162_rn(v.z - __low2float(h1), v.w - __high2float(h1));
    uint2 H, L;
    H.x = *(uint32_t*)&h0; H.y = *(uint32_t*)&h1;
    L.x = *(uint32_t*)&l0; L.y = *(uint32_t*)&l1;
    hi[i] = H;
    lo[i] = L;
}

// ---------------------------------------------------------------------------
// Tensor-core split-bf16 GEMM: C[M,N] = A[M,K] @ B[N,K]^T (+bias/+relu/+res)
// CTA: 128x128 tile, BK=64, 8 warps (warp tile 64x32), 3-stage cp.async.
// smem rows: 64 bf16 = 128 B, SW128 swizzle. Tiles Ah/Al/Bh/Bl x 3 stages.
// ---------------------------------------------------------------------------
enum { EPI_BIAS = 0, EPI_RELU = 1, EPI_RES = 2 };

#define TB 16384                       // one 128x64 bf16 tile
#define GEMM_SMEM (3 * 4 * TB)         // 196608 B

template<int EPI>
__global__ __launch_bounds__(256, 1)
void gemm_tc(const __nv_bfloat16* __restrict__ Ah, const __nv_bfloat16* __restrict__ Al,
             const __nv_bfloat16* __restrict__ Bh, const __nv_bfloat16* __restrict__ Bl,
             const float* __restrict__ bias, const float* __restrict__ Res,
             float* __restrict__ C, int K, int N)
{
    extern __shared__ char smg[];
    const uint32_t sbase = smem_u32(smg);
    const int tid  = threadIdx.x;
    const int lane = tid & 31, wid = tid >> 5;
    const int m0 = blockIdx.y << 7, n0 = blockIdx.x << 7;
    const int wm = (wid & 1) << 6, wn = (wid >> 1) << 5;

    // ---- loader mapping: 8 threads cover one 128B row, 32 rows per pass ----
    const int lrow = tid >> 3;         // 0..31
    const int lkg  = tid & 7;          // 16B group within row
    const __nv_bfloat16* srcs[4];
    srcs[0] = Ah + (size_t)(m0 + lrow) * K + lkg * 8;
    srcs[1] = Al + (size_t)(m0 + lrow) * K + lkg * 8;
    srcs[2] = Bh + (size_t)(n0 + lrow) * K + lkg * 8;
    srcs[3] = Bl + (size_t)(n0 + lrow) * K + lkg * 8;
    uint32_t dbase[4];
    {
        uint32_t sw = swz(lrow * 128 + lkg * 16);
#pragma unroll
        for (int t = 0; t < 4; t++) dbase[t] = sbase + t * TB + sw;
    }

#define LOAD_STAGE(c, s) do {                                               \
    const size_t kb_ = (size_t)(c) << 6;                                    \
    const uint32_t so_ = (uint32_t)(s) * (4 * TB);                          \
    _Pragma("unroll")                                                       \
    for (int t_ = 0; t_ < 4; t_++) {                                        \
        const __nv_bfloat16* sp_ = srcs[t_] + kb_;                          \
        _Pragma("unroll")                                                   \
        for (int j_ = 0; j_ < 4; j_++)                                      \
            CP_ASYNC16(dbase[t_] + so_ + j_ * 4096, sp_ + (size_t)j_ * 32 * K); \
    }                                                                       \
} while (0)

    float acc[4][4][4];
#pragma unroll
    for (int mi = 0; mi < 4; mi++)
#pragma unroll
        for (int ni = 0; ni < 4; ni++)
#pragma unroll
            for (int e = 0; e < 4; e++) acc[mi][ni][e] = 0.f;

    const int nc = K >> 6;
    LOAD_STAGE(0, 0); CP_COMMIT();
    LOAD_STAGE(1, 1); CP_COMMIT();

    for (int c = 0; c < nc; c++) {
        CP_WAIT1();
        __syncthreads();
        if (c + 2 < nc) LOAD_STAGE(c + 2, (c + 2) % 3);
        CP_COMMIT();

        const uint32_t st = (uint32_t)(c % 3) * (4 * TB);
        const uint32_t sAh = sbase + st;
        const uint32_t sAl = sAh + TB;
        const uint32_t sBh = sAl + TB;
        const uint32_t sBl = sBh + TB;
        const uint32_t arow = wm + (lane & 15);
        const uint32_t brow = wn + (lane & 15);

#pragma unroll
        for (int kk = 0; kk < 4; kk++) {
            const uint32_t colb = kk * 32 + ((lane >> 4) << 4);
            uint32_t ah[4][4], al[4][4], bh[4][2], bl[4][2];
#pragma unroll
            for (int mi = 0; mi < 4; mi++) {
                ldsm4(ah[mi], sAh + swz((arow + mi * 16) * 128 + colb));
                ldsm4(al[mi], sAl + swz((arow + mi * 16) * 128 + colb));
            }
#pragma unroll
            for (int nh = 0; nh < 2; nh++) {
                uint32_t r[4];
                ldsm4(r, sBh + swz((brow + nh * 16) * 128 + colb));
                bh[2*nh][0] = r[0]; bh[2*nh][1] = r[2];
                bh[2*nh+1][0] = r[1]; bh[2*nh+1][1] = r[3];
                ldsm4(r, sBl + swz((brow + nh * 16) * 128 + colb));
                bl[2*nh][0] = r[0]; bl[2*nh][1] = r[2];
                bl[2*nh+1][0] = r[1]; bl[2*nh+1][1] = r[3];
            }
#pragma unroll
            for (int mi = 0; mi < 4; mi++)
#pragma unroll
                for (int ni = 0; ni < 4; ni++) {
                    mma16816(acc[mi][ni], ah[mi], bh[ni]);
                    mma16816(acc[mi][ni], ah[mi], bl[ni]);
                    mma16816(acc[mi][ni], al[mi], bh[ni]);
                }
        }
    }

    // ---- epilogue ----
    const int g = lane >> 2, tig = lane & 3;
    float2 bv[4];
#pragma unroll
    for (int ni = 0; ni < 4; ni++)
        bv[ni] = *(const float2*)(bias + n0 + wn + ni * 8 + tig * 2);

#pragma unroll
    for (int mi = 0; mi < 4; mi++) {
        const int r1 = m0 + wm + mi * 16 + g;
        const int r2 = r1 + 8;
#pragma unroll
        for (int ni = 0; ni < 4; ni++) {
            const int col = n0 + wn + ni * 8 + tig * 2;
            float2 v0 = make_float2(acc[mi][ni][0] + bv[ni].x, acc[mi][ni][1] + bv[ni].y);
            float2 v1 = make_float2(acc[mi][ni][2] + bv[ni].x, acc[mi][ni][3] + bv[ni].y);
            if (EPI == EPI_RELU) {
                v0.x = fmaxf(v0.x, 0.f); v0.y = fmaxf(v0.y, 0.f);
                v1.x = fmaxf(v1.x, 0.f); v1.y = fmaxf(v1.y, 0.f);
            }
            if (EPI == EPI_RES) {
                float2 q0 = *(const float2*)(Res + (size_t)r1 * N + col);
                float2 q1 = *(const float2*)(Res + (size_t)r2 * N + col);
                v0.x += q0.x; v0.y += q0.y; v1.x += q1.x; v1.y += q1.y;
            }
            *(float2*)(C + (size_t)r1 * N + col) = v0;
            *(float2*)(C + (size_t)r2 * N + col) = v1;
        }
    }
#undef LOAD_STAGE
}

// ---------------------------------------------------------------------------
// Block-causal flash attention (fp32, known-good). BLK=64 == tile size.
// ---------------------------------------------------------------------------
#define AST 68
#define ATTN_SMEM (3 * 64 * AST * 4)

__global__ __launch_bounds__(256)
void attn_kernel(const float* __restrict__ qkv, float* __restrict__ o)
{
    extern __shared__ float sm[];
    float* Qs = sm;
    float* Ks = sm + 64 * AST;
    float* Vs = sm + 2 * 64 * AST;

    const int jq   = blockIdx.x;
    const int b    = blockIdx.y >> 4;
    const int h    = blockIdx.y & 15;
    const int tid  = threadIdx.x;
    const int lane = tid & 31;
    const int warp = tid >> 5;
    const int r0   = warp << 3;

    const float* qbase = qkv + ((size_t)b * SS + (size_t)jq * 64) * 3072 + h * 64;
    const float* kbase = qkv + (size_t)b * SS * 3072 + 1024 + h * 64;
    const float* vbase = kbase + 1024;

    for (int f = tid; f < 1024; f += 256) {
        int r = f >> 4, c4 = (f & 15) << 2;
        float4 v = *(const float4*)(qbase + (size_t)r * 3072 + c4);
        float* q = &Qs[r * AST + c4];
        q[0] = v.x * 0.125f; q[1] = v.y * 0.125f; q[2] = v.z * 0.125f; q[3] = v.w * 0.125f;
    }

    float O0[8], O1[8], mr[8], lr[8];
#pragma unroll
    for (int i = 0; i < 8; i++) { O0[i] = 0.f; O1[i] = 0.f; mr[i] = -INFINITY; lr[i] = 0.f; }

    for (int kb = 0; kb <= jq; kb++) {
        __syncthreads();
        for (int f = tid; f < 1024; f += 256) {
            int r = f >> 4, c4 = (f & 15) << 2;
            size_t roff = (size_t)(kb * 64 + r) * 3072 + c4;
            float4 kv = *(const float4*)(kbase + roff);
            float4 vv = *(const float4*)(vbase + roff);
            float* kp = &Ks[r * AST + c4];
            float* vp = &Vs[r * AST + c4];
            kp[0] = kv.x; kp[1] = kv.y; kp[2] = kv.z; kp[3] = kv.w;
            vp[0] = vv.x; vp[1] = vv.y; vp[2] = vv.z; vp[3] = vv.w;
        }
        __syncthreads();

        float sc0[8], sc1[8];
#pragma unroll
        for (int i = 0; i < 8; i++) { sc0[i] = 0.f; sc1[i] = 0.f; }
        const float* kr0 = &Ks[(2 * lane) * AST];
        const float* kr1 = kr0 + AST;
#pragma unroll
        for (int d4 = 0; d4 < 64; d4 += 4) {
            float4 k0 = *(const float4*)(kr0 + d4);
            float4 k1 = *(const float4*)(kr1 + d4);
#pragma unroll
            for (int i = 0; i < 8; i++) {
                float4 q = *(const float4*)&Qs[(r0 + i) * AST + d4];
                sc0[i] += q.x * k0.x + q.y * k0.y + q.z * k0.z + q.w * k0.w;
                sc1[i] += q.x * k1.x + q.y * k1.y + q.z * k1.z + q.w * k1.w;
            }
        }
        __syncthreads();

#pragma unroll
        for (int i = 0; i < 8; i++) {
            float mb = fmaxf(sc0[i], sc1[i]);
#pragma unroll
            for (int off = 16; off; off >>= 1) mb = fmaxf(mb, __shfl_xor_sync(0xffffffffu, mb, off));
            float mnew  = fmaxf(mr[i], mb);
            float alpha = __expf(mr[i] - mnew);
            float p0 = __expf(sc0[i] - mnew);
            float p1 = __expf(sc1[i] - mnew);
            float s  = p0 + p1;
#pragma unroll
            for (int off = 16; off; off >>= 1) s += __shfl_xor_sync(0xffffffffu, s, off);
            lr[i] = lr[i] * alpha + s;
            mr[i] = mnew;
            O0[i] *= alpha; O1[i] *= alpha;
            Ks[(r0 + i) * AST + 2 * lane]     = p0;
            Ks[(r0 + i) * AST + 2 * lane + 1] = p1;
        }
        __syncwarp();

#pragma unroll 4
        for (int kc = 0; kc < 64; kc++) {
            float2 v = *(const float2*)&Vs[kc * AST + 2 * lane];
#pragma unroll
            for (int i = 0; i < 8; i++) {
                float p = Ks[(r0 + i) * AST + kc];
                O0[i] += p * v.x;
                O1[i] += p * v.y;
            }
        }
    }

    float* obase = o + ((size_t)b * SS + (size_t)jq * 64) * DD + h * 64;
#pragma unroll
    for (int i = 0; i < 8; i++) {
        float inv = 1.0f / lr[i];
        *(float2*)(obase + (size_t)(r0 + i) * DD + 2 * lane) =
            make_float2(O0[i] * inv, O1[i] * inv);
    }
}

// ---------------------------------------------------------------------------
// LayerNorm over D=1024, one block (256 threads) per row
// ---------------------------------------------------------------------------
__global__ __launch_bounds__(256)
void ln_kernel(const float* __restrict__ in, const float* __restrict__ w,
               const float* __restrict__ b, float* __restrict__ out)
{
    __shared__ float s_sum[8], s_sq[8], s_bc[2];
    const int row = blockIdx.x, tid = threadIdx.x;
    float4 v = ((const float4*)(in + (size_t)row * 1024))[tid];
    float s = v.x + v.y + v.z + v.w;
    float q = v.x * v.x + v.y * v.y + v.z * v.z + v.w * v.w;
#pragma unroll
    for (int o = 16; o; o >>= 1) {
        s += __shfl_xor_sync(0xffffffffu, s, o);
        q += __shfl_xor_sync(0xffffffffu, q, o);
    }
    if ((tid & 31) == 0) { s_sum[tid >> 5] = s; s_sq[tid >> 5] = q; }
    __syncthreads();
    if (tid == 0) {
        float ts = 0.f, tq = 0.f;
#pragma unroll
        for (int i = 0; i < 8; i++) { ts += s_sum[i]; tq += s_sq[i]; }
        float mu  = ts * (1.f / 1024.f);
        float var = tq * (1.f / 1024.f) - mu * mu;
        s_bc[0] = mu;
        s_bc[1] = rsqrtf(var + 1e-5f);
    }
    __syncthreads();
    float mu = s_bc[0], rs = s_bc[1];
    float4 wv = ((const float4*)w)[tid];
    float4 bv = ((const float4*)b)[tid];
    float4 ov;
    ov.x = (v.x - mu) * rs * wv.x + bv.x;
    ov.y = (v.y - mu) * rs * wv.y + bv.y;
    ov.z = (v.z - mu) * rs * wv.z + bv.z;
    ov.w = (v.w - mu) * rs * wv.w + bv.w;
    ((float4*)(out + (size_t)row * 1024))[tid] = ov;
}

__global__ void copy_kernel(const float4* __restrict__ s, float4* __restrict__ d)
{
    int i = blockIdx.x * 256 + threadIdx.x;
    d[i] = s[i];
}

// ---------------------------------------------------------------------------
// Host orchestration (graph-capturable: kernel launches only)
// ---------------------------------------------------------------------------
extern "C" void kernel_launch(void* const* d_in, const int* in_sizes, int n_in,
                              void* d_out, int out_size)
{
    (void)in_sizes; (void)n_in; (void)out_size;
    const float* x_in = (const float*)d_in[0];
    const float* ipw  = (const float*)d_in[1];   // [L,3072,1024]
    const float* ipb  = (const float*)d_in[2];   // [L,3072]
    const float* ow   = (const float*)d_in[3];   // [L,1024,1024]
    const float* ob   = (const float*)d_in[4];   // [L,1024]
    const float* n1w  = (const float*)d_in[5];
    const float* n1b  = (const float*)d_in[6];
    const float* f1w  = (const float*)d_in[7];   // [L,4096,1024]
    const float* f1b  = (const float*)d_in[8];   // [L,4096]
    const float* f2w  = (const float*)d_in[9];   // [L,1024,4096]
    const float* f2b  = (const float*)d_in[10];  // [L,1024]
    const float* n2w  = (const float*)d_in[11];
    const float* n2b  = (const float*)d_in[12];
    float* out = (float*)d_out;

    float *px, *pqkv, *po, *ph, *ptmp;
    __nv_bfloat16 *pah, *pal, *pwh, *pwl;
    cudaGetSymbolAddress((void**)&px,   g_x);
    cudaGetSymbolAddress((void**)&pqkv, g_qkv);
    cudaGetSymbolAddress((void**)&po,   g_o);
    cudaGetSymbolAddress((void**)&ph,   g_h);
    cudaGetSymbolAddress((void**)&ptmp, g_tmp);
    cudaGetSymbolAddress((void**)&pah,  g_ah);
    cudaGetSymbolAddress((void**)&pal,  g_al);
    cudaGetSymbolAddress((void**)&pwh,  g_wh);
    cudaGetSymbolAddress((void**)&pwl,  g_wl);

    cudaFuncSetAttribute((const void*)attn_kernel,
                         cudaFuncAttributeMaxDynamicSharedMemorySize, ATTN_SMEM);
    cudaFuncSetAttribute((const void*)gemm_tc<EPI_BIAS>,
                         cudaFuncAttributeMaxDynamicSharedMemorySize, GEMM_SMEM);
    cudaFuncSetAttribute((const void*)gemm_tc<EPI_RELU>,
                         cudaFuncAttributeMaxDynamicSharedMemorySize, GEMM_SMEM);
    cudaFuncSetAttribute((const void*)gemm_tc<EPI_RES>,
                         cudaFuncAttributeMaxDynamicSharedMemorySize, GEMM_SMEM);

#define SPLIT(src, hi, lo, nelem) \
    split_kernel<<<((nelem)/4 + 255)/256, 256>>>((const float4*)(src), (uint2*)(hi), (uint2*)(lo), (nelem)/4)

    // x -> working buffer
    copy_kernel<<<4096, 256>>>((const float4*)x_in, (float4*)px);

    for (int l = 0; l < NLAYERS; l++) {
        const float* Wqkv = ipw + (size_t)l * 3 * DD * DD;
        const float* Bqkv = ipb + (size_t)l * 3 * DD;
        const float* Wout = ow  + (size_t)l * DD * DD;
        const float* Bout = ob  + (size_t)l * DD;
        const float* W1   = f1w + (size_t)l * DFF * DD;
        const float* B1   = f1b + (size_t)l * DFF;
        const float* W2   = f2w + (size_t)l * DD * DFF;
        const float* B2   = f2b + (size_t)l * DD;

        // qkv = x @ Wqkv^T + b
        SPLIT(px,   pah, pal, MM * DD);
        SPLIT(Wqkv, pwh, pwl, 3 * DD * DD);
        gemm_tc<EPI_BIAS><<<dim3(24, 32), 256, GEMM_SMEM>>>(
            pah, pal, pwh, pwl, Bqkv, nullptr, pqkv, DD, 3 * DD);

        // block-causal attention
        attn_kernel<<<dim3(SS / 64, BB * HH), 256, ATTN_SMEM>>>(pqkv, po);

        // tmp = x + o @ Wout^T + b
        SPLIT(po,   pah, pal, MM * DD);
        SPLIT(Wout, pwh, pwl, DD * DD);
        gemm_tc<EPI_RES><<<dim3(8, 32), 256, GEMM_SMEM>>>(
            pah, pal, pwh, pwl, Bout, px, ptmp, DD, DD);
        ln_kernel<<<MM, 256>>>(ptmp, n1w + (size_t)l * DD, n1b + (size_t)l * DD, px);

        // h = relu(x @ W1^T + b1)
        SPLIT(px, pah, pal, MM * DD);
        SPLIT(W1, pwh, pwl, DFF * DD);
        gemm_tc<EPI_RELU><<<dim3(32, 32), 256, GEMM_SMEM>>>(
            pah, pal, pwh, pwl, B1, nullptr, ph, DD, DFF);

        // tmp = x + h @ W2^T + b2
        SPLIT(ph, pah, pal, MM * DFF);
        SPLIT(W2, pwh, pwl, DD * DFF);
        gemm_tc<EPI_RES><<<dim3(8, 32), 256, GEMM_SMEM>>>(
            pah, pal, pwh, pwl, B2, px, ptmp, DFF, DD);
        ln_kernel<<<MM, 256>>>(ptmp, n2w + (size_t)l * DD, n2b + (size_t)l * DD,
                               (l == NLAYERS - 1) ? out : px);
    }
#undef SPLIT
}

// round 12
// speedup vs baseline: 1.9371x; 1.0016x over previous
#include <cuda_runtime.h>
#include <cuda_bf16.h>
#include <math.h>
#include <stdint.h>

// Problem constants
#define BB 4
#define SS 1024
#define DD 1024
#define HH 16
#define DFF 4096
#define NLAYERS 4
#define MM (BB*SS)          // 4096 rows

// ---------------------------------------------------------------------------
// Scratch (static device globals -- no allocation allowed)
// ---------------------------------------------------------------------------
__device__ float g_x  [(size_t)MM * DD];        // activations
__device__ float g_qkv[(size_t)MM * 3 * DD];
__device__ float g_o  [(size_t)MM * DD];
__device__ float g_h  [(size_t)MM * DFF];
__device__ float g_tmp[(size_t)MM * DD];
// split-bf16 operand buffers (reused per GEMM, graph executes sequentially)
__device__ __nv_bfloat16 g_ah[(size_t)MM * DFF];          // A hi (max 16M elems)
__device__ __nv_bfloat16 g_al[(size_t)MM * DFF];          // A lo
__device__ __nv_bfloat16 g_wh[(size_t)4 * 1024 * 1024];   // W hi (max 4M elems)
__device__ __nv_bfloat16 g_wl[(size_t)4 * 1024 * 1024];   // W lo

// ---------------------------------------------------------------------------
// Helpers
// ---------------------------------------------------------------------------
__device__ __forceinline__ uint32_t smem_u32(const void* p) {
    uint32_t a;
    asm("{ .reg .u64 t; cvta.to.shared.u64 t, %1; cvt.u32.u64 %0, t; }"
        : "=r"(a) : "l"(p));
    return a;
}
__device__ __forceinline__ uint32_t swz(uint32_t off) {
    return off ^ ((off >> 3) & 0x70);
}

#define CP_ASYNC16(dst, src) \
    asm volatile("cp.async.cg.shared.global [%0], [%1], 16;" :: "r"(dst), "l"(src))
#define CP_COMMIT() asm volatile("cp.async.commit_group;")
#define CP_WAIT1()  asm volatile("cp.async.wait_group 1;")

__device__ __forceinline__ void ldsm4(uint32_t* r, uint32_t addr) {
    asm volatile("ldmatrix.sync.aligned.m8n8.x4.shared.b16 {%0,%1,%2,%3}, [%4];"
        : "=r"(r[0]), "=r"(r[1]), "=r"(r[2]), "=r"(r[3]) : "r"(addr));
}
__device__ __forceinline__ void mma16816(float* d, const uint32_t* a, const uint32_t* b) {
    asm volatile(
        "mma.sync.aligned.m16n8k16.row.col.f32.bf16.bf16.f32 "
        "{%0,%1,%2,%3}, {%4,%5,%6,%7}, {%8,%9}, {%0,%1,%2,%3};"
        : "+f"(d[0]), "+f"(d[1]), "+f"(d[2]), "+f"(d[3])
        : "r"(a[0]), "r"(a[1]), "r"(a[2]), "r"(a[3]), "r"(b[0]), "r"(b[1]));
}

// ---------------------------------------------------------------------------
// fp32 -> (hi, lo) bf16 split (elementwise, memory-bound)
// ---------------------------------------------------------------------------
__global__ __launch_bounds__(256)
void split_kernel(const float4* __restrict__ in, uint2* __restrict__ hi,
                  uint2* __restrict__ lo, int n4)
{
    int i = blockIdx.x * 256 + threadIdx.x;
    if (i >= n4) return;
    float4 v = in[i];
    __nv_bfloat162 h0 = __floats2bfloat162_rn(v.x, v.y);
    __nv_bfloat162 h1 = __floats2bfloat162_rn(v.z, v.w);
    __nv_bfloat162 l0 = __floats2bfloat162_rn(v.x - __low2float(h0), v.y - __high2float(h0));
    __nv_bfloat162 l1 = __floats2bfloat162_rn(v.z - __low2float(h1), v.w - __high2float(h1));
    uint2 H, L;
    H.x = *(uint32_t*)&h0; H.y = *(uint32_t*)&h1;
    L.x = *(uint32_t*)&l0; L.y = *(uint32_t*)&l1;
    hi[i] = H;
    lo[i] = L;
}

// ---------------------------------------------------------------------------
// Tensor-core split-bf16 GEMM: C[M,N] = A[M,K] @ B[N,K]^T (+bias/+relu/+res)
// CTA: 128x128 tile, BK=64, 16 warps (warp tile 32x32), 3-stage cp.async.
// smem rows: 64 bf16 = 128 B, SW128 swizzle. Tiles Ah/Al/Bh/Bl x 3 stages.
// ---------------------------------------------------------------------------
enum { EPI_BIAS = 0, EPI_RELU = 1, EPI_RES = 2 };

#define TB 16384                       // one 128x64 bf16 tile
#define GEMM_SMEM (3 * 4 * TB)         // 196608 B

template<int EPI>
__global__ __launch_bounds__(512, 1)
void gemm_tc(const __nv_bfloat16* __restrict__ Ah, const __nv_bfloat16* __restrict__ Al,
             const __nv_bfloat16* __restrict__ Bh, const __nv_bfloat16* __restrict__ Bl,
             const float* __restrict__ bias, const float* __restrict__ Res,
             float* __restrict__ C, int K, int N)
{
    extern __shared__ char smg[];
    const uint32_t sbase = smem_u32(smg);
    const int tid  = threadIdx.x;
    const int lane = tid & 31, wid = tid >> 5;       // 16 warps
    const int m0 = blockIdx.y << 7, n0 = blockIdx.x << 7;
    const int wm = (wid & 3) << 5;                   // 0,32,64,96
    const int wn = (wid >> 2) << 5;                  // 0,32,64,96

    // ---- loader mapping: 8 threads cover one 128B row, 64 rows per pass ----
    const int lrow = tid >> 3;         // 0..63
    const int lkg  = tid & 7;          // 16B group within row
    const __nv_bfloat16* srcs[4];
    srcs[0] = Ah + (size_t)(m0 + lrow) * K + lkg * 8;
    srcs[1] = Al + (size_t)(m0 + lrow) * K + lkg * 8;
    srcs[2] = Bh + (size_t)(n0 + lrow) * K + lkg * 8;
    srcs[3] = Bl + (size_t)(n0 + lrow) * K + lkg * 8;
    uint32_t dbase[4];
    {
        uint32_t sw = swz(lrow * 128 + lkg * 16);
#pragma unroll
        for (int t = 0; t < 4; t++) dbase[t] = sbase + t * TB + sw;
    }

#define LOAD_STAGE(c, s) do {                                               \
    const size_t kb_ = (size_t)(c) << 6;                                    \
    const uint32_t so_ = (uint32_t)(s) * (4 * TB);                          \
    _Pragma("unroll")                                                       \
    for (int t_ = 0; t_ < 4; t_++) {                                        \
        const __nv_bfloat16* sp_ = srcs[t_] + kb_;                          \
        _Pragma("unroll")                                                   \
        for (int j_ = 0; j_ < 2; j_++)                                      \
            CP_ASYNC16(dbase[t_] + so_ + j_ * 8192, sp_ + (size_t)j_ * 64 * K); \
    }                                                                       \
} while (0)

    float acc[2][4][4];
#pragma unroll
    for (int mi = 0; mi < 2; mi++)
#pragma unroll
        for (int ni = 0; ni < 4; ni++)
#pragma unroll
            for (int e = 0; e < 4; e++) acc[mi][ni][e] = 0.f;

    const int nc = K >> 6;
    LOAD_STAGE(0, 0); CP_COMMIT();
    LOAD_STAGE(1, 1); CP_COMMIT();

    // Fragment addressing: row within tile steps by multiples of 16, so the
    // SW128 xor constant (row&7)<<4 is invariant per thread.
    const uint32_t arow = wm + (lane & 15);
    const uint32_t brow = wn + (lane & 15);
    const uint32_t axor = (arow & 7) << 4;
    const uint32_t bxor = (brow & 7) << 4;
    const uint32_t chalf = (lane >> 4) << 4;         // 0 or 16 within k-block

    for (int c = 0; c < nc; c++) {
        CP_WAIT1();
        __syncthreads();
        if (c + 2 < nc) LOAD_STAGE(c + 2, (c + 2) % 3);
        CP_COMMIT();

        const uint32_t st = (uint32_t)(c % 3) * (4 * TB);
        const uint32_t aAh = sbase + st + arow * 128;
        const uint32_t aAl = aAh + TB;
        const uint32_t aBh = sbase + st + 2 * TB + brow * 128;
        const uint32_t aBl = aBh + TB;

#pragma unroll
        for (int kk = 0; kk < 4; kk++) {
            const uint32_t ca = (kk * 32 + chalf) ^ axor;
            const uint32_t cb = (kk * 32 + chalf) ^ bxor;
            uint32_t ah[2][4], al[2][4], bh[4][2], bl[4][2];
#pragma unroll
            for (int mi = 0; mi < 2; mi++) {
                ldsm4(ah[mi], aAh + mi * (16 * 128) + ca);
                ldsm4(al[mi], aAl + mi * (16 * 128) + ca);
            }
#pragma unroll
            for (int nh = 0; nh < 2; nh++) {
                uint32_t r[4];
                ldsm4(r, aBh + nh * (16 * 128) + cb);
                bh[2*nh][0] = r[0]; bh[2*nh][1] = r[2];
                bh[2*nh+1][0] = r[1]; bh[2*nh+1][1] = r[3];
                ldsm4(r, aBl + nh * (16 * 128) + cb);
                bl[2*nh][0] = r[0]; bl[2*nh][1] = r[2];
                bl[2*nh+1][0] = r[1]; bl[2*nh+1][1] = r[3];
            }
#pragma unroll
            for (int mi = 0; mi < 2; mi++)
#pragma unroll
                for (int ni = 0; ni < 4; ni++) {
                    mma16816(acc[mi][ni], ah[mi], bh[ni]);
                    mma16816(acc[mi][ni], ah[mi], bl[ni]);
                    mma16816(acc[mi][ni], al[mi], bh[ni]);
                }
        }
    }

    // ---- epilogue ----
    const int g = lane >> 2, tig = lane & 3;
    float2 bv[4];
#pragma unroll
    for (int ni = 0; ni < 4; ni++)
        bv[ni] = *(const float2*)(bias + n0 + wn + ni * 8 + tig * 2);

#pragma unroll
    for (int mi = 0; mi < 2; mi++) {
        const int r1 = m0 + wm + mi * 16 + g;
        const int r2 = r1 + 8;
#pragma unroll
        for (int ni = 0; ni < 4; ni++) {
            const int col = n0 + wn + ni * 8 + tig * 2;
            float2 v0 = make_float2(acc[mi][ni][0] + bv[ni].x, acc[mi][ni][1] + bv[ni].y);
            float2 v1 = make_float2(acc[mi][ni][2] + bv[ni].x, acc[mi][ni][3] + bv[ni].y);
            if (EPI == EPI_RELU) {
                v0.x = fmaxf(v0.x, 0.f); v0.y = fmaxf(v0.y, 0.f);
                v1.x = fmaxf(v1.x, 0.f); v1.y = fmaxf(v1.y, 0.f);
            }
            if (EPI == EPI_RES) {
                float2 q0 = *(const float2*)(Res + (size_t)r1 * N + col);
                float2 q1 = *(const float2*)(Res + (size_t)r2 * N + col);
                v0.x += q0.x; v0.y += q0.y; v1.x += q1.x; v1.y += q1.y;
            }
            *(float2*)(C + (size_t)r1 * N + col) = v0;
            *(float2*)(C + (size_t)r2 * N + col) = v1;
        }
    }
#undef LOAD_STAGE
}

// ---------------------------------------------------------------------------
// Block-causal flash attention (fp32, known-good). BLK=64 == tile size.
// ---------------------------------------------------------------------------
#define AST 68
#define ATTN_SMEM (3 * 64 * AST * 4)

__global__ __launch_bounds__(256)
void attn_kernel(const float* __restrict__ qkv, float* __restrict__ o)
{
    extern __shared__ float sm[];
    float* Qs = sm;
    float* Ks = sm + 64 * AST;
    float* Vs = sm + 2 * 64 * AST;

    const int jq   = blockIdx.x;
    const int b    = blockIdx.y >> 4;
    const int h    = blockIdx.y & 15;
    const int tid  = threadIdx.x;
    const int lane = tid & 31;
    const int warp = tid >> 5;
    const int r0   = warp << 3;

    const float* qbase = qkv + ((size_t)b * SS + (size_t)jq * 64) * 3072 + h * 64;
    const float* kbase = qkv + (size_t)b * SS * 3072 + 1024 + h * 64;
    const float* vbase = kbase + 1024;

    for (int f = tid; f < 1024; f += 256) {
        int r = f >> 4, c4 = (f & 15) << 2;
        float4 v = *(const float4*)(qbase + (size_t)r * 3072 + c4);
        float* q = &Qs[r * AST + c4];
        q[0] = v.x * 0.125f; q[1] = v.y * 0.125f; q[2] = v.z * 0.125f; q[3] = v.w * 0.125f;
    }

    float O0[8], O1[8], mr[8], lr[8];
#pragma unroll
    for (int i = 0; i < 8; i++) { O0[i] = 0.f; O1[i] = 0.f; mr[i] = -INFINITY; lr[i] = 0.f; }

    for (int kb = 0; kb <= jq; kb++) {
        __syncthreads();
        for (int f = tid; f < 1024; f += 256) {
            int r = f >> 4, c4 = (f & 15) << 2;
            size_t roff = (size_t)(kb * 64 + r) * 3072 + c4;
            float4 kv = *(const float4*)(kbase + roff);
            float4 vv = *(const float4*)(vbase + roff);
            float* kp = &Ks[r * AST + c4];
            float* vp = &Vs[r * AST + c4];
            kp[0] = kv.x; kp[1] = kv.y; kp[2] = kv.z; kp[3] = kv.w;
            vp[0] = vv.x; vp[1] = vv.y; vp[2] = vv.z; vp[3] = vv.w;
        }
        __syncthreads();

        float sc0[8], sc1[8];
#pragma unroll
        for (int i = 0; i < 8; i++) { sc0[i] = 0.f; sc1[i] = 0.f; }
        const float* kr0 = &Ks[(2 * lane) * AST];
        const float* kr1 = kr0 + AST;
#pragma unroll
        for (int d4 = 0; d4 < 64; d4 += 4) {
            float4 k0 = *(const float4*)(kr0 + d4);
            float4 k1 = *(const float4*)(kr1 + d4);
#pragma unroll
            for (int i = 0; i < 8; i++) {
                float4 q = *(const float4*)&Qs[(r0 + i) * AST + d4];
                sc0[i] += q.x * k0.x + q.y * k0.y + q.z * k0.z + q.w * k0.w;
                sc1[i] += q.x * k1.x + q.y * k1.y + q.z * k1.z + q.w * k1.w;
            }
        }
        __syncthreads();

#pragma unroll
        for (int i = 0; i < 8; i++) {
            float mb = fmaxf(sc0[i], sc1[i]);
#pragma unroll
            for (int off = 16; off; off >>= 1) mb = fmaxf(mb, __shfl_xor_sync(0xffffffffu, mb, off));
            float mnew  = fmaxf(mr[i], mb);
            float alpha = __expf(mr[i] - mnew);
            float p0 = __expf(sc0[i] - mnew);
            float p1 = __expf(sc1[i] - mnew);
            float s  = p0 + p1;
#pragma unroll
            for (int off = 16; off; off >>= 1) s += __shfl_xor_sync(0xffffffffu, s, off);
            lr[i] = lr[i] * alpha + s;
            mr[i] = mnew;
            O0[i] *= alpha; O1[i] *= alpha;
            Ks[(r0 + i) * AST + 2 * lane]     = p0;
            Ks[(r0 + i) * AST + 2 * lane + 1] = p1;
        }
        __syncwarp();

#pragma unroll 4
        for (int kc = 0; kc < 64; kc++) {
            float2 v = *(const float2*)&Vs[kc * AST + 2 * lane];
#pragma unroll
            for (int i = 0; i < 8; i++) {
                float p = Ks[(r0 + i) * AST + kc];
                O0[i] += p * v.x;
                O1[i] += p * v.y;
            }
        }
    }

    float* obase = o + ((size_t)b * SS + (size_t)jq * 64) * DD + h * 64;
#pragma unroll
    for (int i = 0; i < 8; i++) {
        float inv = 1.0f / lr[i];
        *(float2*)(obase + (size_t)(r0 + i) * DD + 2 * lane) =
            make_float2(O0[i] * inv, O1[i] * inv);
    }
}

// ---------------------------------------------------------------------------
// LayerNorm over D=1024, one block (256 threads) per row
// ---------------------------------------------------------------------------
__global__ __launch_bounds__(256)
void ln_kernel(const float* __restrict__ in, const float* __restrict__ w,
               const float* __restrict__ b, float* __restrict__ out)
{
    __shared__ float s_sum[8], s_sq[8], s_bc[2];
    const int row = blockIdx.x, tid = threadIdx.x;
    float4 v = ((const float4*)(in + (size_t)row * 1024))[tid];
    float s = v.x + v.y + v.z + v.w;
    float q = v.x * v.x + v.y * v.y + v.z * v.z + v.w * v.w;
#pragma unroll
    for (int o = 16; o; o >>= 1) {
        s += __shfl_xor_sync(0xffffffffu, s, o);
        q += __shfl_xor_sync(0xffffffffu, q, o);
    }
    if ((tid & 31) == 0) { s_sum[tid >> 5] = s; s_sq[tid >> 5] = q; }
    __syncthreads();
    if (tid == 0) {
        float ts = 0.f, tq = 0.f;
#pragma unroll
        for (int i = 0; i < 8; i++) { ts += s_sum[i]; tq += s_sq[i]; }
        float mu  = ts * (1.f / 1024.f);
        float var = tq * (1.f / 1024.f) - mu * mu;
        s_bc[0] = mu;
        s_bc[1] = rsqrtf(var + 1e-5f);
    }
    __syncthreads();
    float mu = s_bc[0], rs = s_bc[1];
    float4 wv = ((const float4*)w)[tid];
    float4 bv = ((const float4*)b)[tid];
    float4 ov;
    ov.x = (v.x - mu) * rs * wv.x + bv.x;
    ov.y = (v.y - mu) * rs * wv.y + bv.y;
    ov.z = (v.z - mu) * rs * wv.z + bv.z;
    ov.w = (v.w - mu) * rs * wv.w + bv.w;
    ((float4*)(out + (size_t)row * 1024))[tid] = ov;
}

__global__ void copy_kernel(const float4* __restrict__ s, float4* __restrict__ d)
{
    int i = blockIdx.x * 256 + threadIdx.x;
    d[i] = s[i];
}

// ---------------------------------------------------------------------------
// Host orchestration (graph-capturable: kernel launches only)
// ---------------------------------------------------------------------------
extern "C" void kernel_launch(void* const* d_in, const int* in_sizes, int n_in,
                              void* d_out, int out_size)
{
    (void)in_sizes; (void)n_in; (void)out_size;
    const float* x_in = (const float*)d_in[0];
    const float* ipw  = (const float*)d_in[1];   // [L,3072,1024]
    const float* ipb  = (const float*)d_in[2];   // [L,3072]
    const float* ow   = (const float*)d_in[3];   // [L,1024,1024]
    const float* ob   = (const float*)d_in[4];   // [L,1024]
    const float* n1w  = (const float*)d_in[5];
    const float* n1b  = (const float*)d_in[6];
    const float* f1w  = (const float*)d_in[7];   // [L,4096,1024]
    const float* f1b  = (const float*)d_in[8];   // [L,4096]
    const float* f2w  = (const float*)d_in[9];   // [L,1024,4096]
    const float* f2b  = (const float*)d_in[10];  // [L,1024]
    const float* n2w  = (const float*)d_in[11];
    const float* n2b  = (const float*)d_in[12];
    float* out = (float*)d_out;

    float *px, *pqkv, *po, *ph, *ptmp;
    __nv_bfloat16 *pah, *pal, *pwh, *pwl;
    cudaGetSymbolAddress((void**)&px,   g_x);
    cudaGetSymbolAddress((void**)&pqkv, g_qkv);
    cudaGetSymbolAddress((void**)&po,   g_o);
    cudaGetSymbolAddress((void**)&ph,   g_h);
    cudaGetSymbolAddress((void**)&ptmp, g_tmp);
    cudaGetSymbolAddress((void**)&pah,  g_ah);
    cudaGetSymbolAddress((void**)&pal,  g_al);
    cudaGetSymbolAddress((void**)&pwh,  g_wh);
    cudaGetSymbolAddress((void**)&pwl,  g_wl);

    cudaFuncSetAttribute((const void*)attn_kernel,
                         cudaFuncAttributeMaxDynamicSharedMemorySize, ATTN_SMEM);
    cudaFuncSetAttribute((const void*)gemm_tc<EPI_BIAS>,
                         cudaFuncAttributeMaxDynamicSharedMemorySize, GEMM_SMEM);
    cudaFuncSetAttribute((const void*)gemm_tc<EPI_RELU>,
                         cudaFuncAttributeMaxDynamicSharedMemorySize, GEMM_SMEM);
    cudaFuncSetAttribute((const void*)gemm_tc<EPI_RES>,
                         cudaFuncAttributeMaxDynamicSharedMemorySize, GEMM_SMEM);

#define SPLIT(src, hi, lo, nelem) \
    split_kernel<<<((nelem)/4 + 255)/256, 256>>>((const float4*)(src), (uint2*)(hi), (uint2*)(lo), (nelem)/4)

    // x -> working buffer
    copy_kernel<<<4096, 256>>>((const float4*)x_in, (float4*)px);

    for (int l = 0; l < NLAYERS; l++) {
        const float* Wqkv = ipw + (size_t)l * 3 * DD * DD;
        const float* Bqkv = ipb + (size_t)l * 3 * DD;
        const float* Wout = ow  + (size_t)l * DD * DD;
        const float* Bout = ob  + (size_t)l * DD;
        const float* W1   = f1w + (size_t)l * DFF * DD;
        const float* B1   = f1b + (size_t)l * DFF;
        const float* W2   = f2w + (size_t)l * DD * DFF;
        const float* B2   = f2b + (size_t)l * DD;

        // qkv = x @ Wqkv^T + b
        SPLIT(px,   pah, pal, MM * DD);
        SPLIT(Wqkv, pwh, pwl, 3 * DD * DD);
        gemm_tc<EPI_BIAS><<<dim3(24, 32), 512, GEMM_SMEM>>>(
            pah, pal, pwh, pwl, Bqkv, nullptr, pqkv, DD, 3 * DD);

        // block-causal attention
        attn_kernel<<<dim3(SS / 64, BB * HH), 256, ATTN_SMEM>>>(pqkv, po);

        // tmp = x + o @ Wout^T + b
        SPLIT(po,   pah, pal, MM * DD);
        SPLIT(Wout, pwh, pwl, DD * DD);
        gemm_tc<EPI_RES><<<dim3(8, 32), 512, GEMM_SMEM>>>(
            pah, pal, pwh, pwl, Bout, px, ptmp, DD, DD);
        ln_kernel<<<MM, 256>>>(ptmp, n1w + (size_t)l * DD, n1b + (size_t)l * DD, px);

        // h = relu(x @ W1^T + b1)
        SPLIT(px, pah, pal, MM * DD);
        SPLIT(W1, pwh, pwl, DFF * DD);
        gemm_tc<EPI_RELU><<<dim3(32, 32), 512, GEMM_SMEM>>>(
            pah, pal, pwh, pwl, B1, nullptr, ph, DD, DFF);

        // tmp = x + h @ W2^T + b2
        SPLIT(ph, pah, pal, MM * DFF);
        SPLIT(W2, pwh, pwl, DD * DFF);
        gemm_tc<EPI_RES><<<dim3(8, 32), 512, GEMM_SMEM>>>(
            pah, pal, pwh, pwl, B2, px, ptmp, DFF, DD);
        ln_kernel<<<MM, 256>>>(ptmp, n2w + (size_t)l * DD, n2b + (size_t)l * DD,
                               (l == NLAYERS - 1) ? out : px);
    }
#undef SPLIT
}

// round 13
// speedup vs baseline: 1.9959x; 1.0303x over previous
#include <cuda_runtime.h>
#include <cuda_bf16.h>
#include <math.h>
#include <stdint.h>

// Problem constants
#define BB 4
#define SS 1024
#define DD 1024
#define HH 16
#define DFF 4096
#define NLAYERS 4
#define MM (BB*SS)          // 4096 rows

// ---------------------------------------------------------------------------
// Scratch (static device globals -- no allocation allowed)
// ---------------------------------------------------------------------------
__device__ float g_x  [(size_t)MM * DD];        // activations (fp32, residual)
__device__ float g_qkv[(size_t)MM * 3 * DD];
__device__ float g_tmp[(size_t)MM * DD];        // pre-LN buffer
// split-bf16 activation buffers
__device__ __nv_bfloat16 g_xh[(size_t)MM * DD];           // x hi (LN output)
__device__ __nv_bfloat16 g_xl[(size_t)MM * DD];           // x lo
__device__ __nv_bfloat16 g_oh[(size_t)MM * DD];           // attn-out hi
__device__ __nv_bfloat16 g_ol[(size_t)MM * DD];           // attn-out lo
__device__ __nv_bfloat16 g_ah[(size_t)MM * DFF];          // FF hidden hi
__device__ __nv_bfloat16 g_al[(size_t)MM * DFF];          // FF hidden lo
__device__ __nv_bfloat16 g_wh[(size_t)4 * 1024 * 1024];   // W hi (max 4M elems)
__device__ __nv_bfloat16 g_wl[(size_t)4 * 1024 * 1024];   // W lo

// ---------------------------------------------------------------------------
// Helpers
// ---------------------------------------------------------------------------
__device__ __forceinline__ uint32_t smem_u32(const void* p) {
    uint32_t a;
    asm("{ .reg .u64 t; cvta.to.shared.u64 t, %1; cvt.u32.u64 %0, t; }"
        : "=r"(a) : "l"(p));
    return a;
}
__device__ __forceinline__ uint32_t swz(uint32_t off) {
    return off ^ ((off >> 3) & 0x70);
}
// pack two floats into bf16x2 (hi) and residual bf16x2 (lo)
__device__ __forceinline__ void split2(float x, float y, uint32_t& H, uint32_t& L) {
    __nv_bfloat162 h = __floats2bfloat162_rn(x, y);
    __nv_bfloat162 l = __floats2bfloat162_rn(x - __low2float(h), y - __high2float(h));
    H = *(uint32_t*)&h;
    L = *(uint32_t*)&l;
}

#define CP_ASYNC16(dst, src) \
    asm volatile("cp.async.cg.shared.global [%0], [%1], 16;" :: "r"(dst), "l"(src))
#define CP_COMMIT() asm volatile("cp.async.commit_group;")
#define CP_WAIT1()  asm volatile("cp.async.wait_group 1;")

__device__ __forceinline__ void ldsm4(uint32_t* r, uint32_t addr) {
    asm volatile("ldmatrix.sync.aligned.m8n8.x4.shared.b16 {%0,%1,%2,%3}, [%4];"
        : "=r"(r[0]), "=r"(r[1]), "=r"(r[2]), "=r"(r[3]) : "r"(addr));
}
__device__ __forceinline__ void mma16816(float* d, const uint32_t* a, const uint32_t* b) {
    asm volatile(
        "mma.sync.aligned.m16n8k16.row.col.f32.bf16.bf16.f32 "
        "{%0,%1,%2,%3}, {%4,%5,%6,%7}, {%8,%9}, {%0,%1,%2,%3};"
        : "+f"(d[0]), "+f"(d[1]), "+f"(d[2]), "+f"(d[3])
        : "r"(a[0]), "r"(a[1]), "r"(a[2]), "r"(a[3]), "r"(b[0]), "r"(b[1]));
}

// ---------------------------------------------------------------------------
// fp32 -> (hi, lo) bf16 split (weights only now)
// ---------------------------------------------------------------------------
__global__ __launch_bounds__(256)
void split_kernel(const float4* __restrict__ in, uint2* __restrict__ hi,
                  uint2* __restrict__ lo, int n4)
{
    int i = blockIdx.x * 256 + threadIdx.x;
    if (i >= n4) return;
    float4 v = in[i];
    uint2 H, L;
    split2(v.x, v.y, H.x, L.x);
    split2(v.z, v.w, H.y, L.y);
    hi[i] = H;
    lo[i] = L;
}

// ---------------------------------------------------------------------------
// Tensor-core split-bf16 GEMM: C[M,N] = A[M,K] @ B[N,K]^T (+bias/+relu/+res)
// CTA: 128x128 tile, BK=64, 16 warps (warp tile 32x32), 3-stage cp.async.
// EPI_RELU writes split-bf16 (Ch/Cl); others write fp32 C.
// ---------------------------------------------------------------------------
enum { EPI_BIAS = 0, EPI_RELU = 1, EPI_RES = 2 };

#define TB 16384                       // one 128x64 bf16 tile
#define GEMM_SMEM (3 * 4 * TB)         // 196608 B

template<int EPI>
__global__ __launch_bounds__(512, 1)
void gemm_tc(const __nv_bfloat16* __restrict__ Ah, const __nv_bfloat16* __restrict__ Al,
             const __nv_bfloat16* __restrict__ Bh, const __nv_bfloat16* __restrict__ Bl,
             const float* __restrict__ bias, const float* __restrict__ Res,
             float* __restrict__ C,
             __nv_bfloat16* __restrict__ Ch, __nv_bfloat16* __restrict__ Cl,
             int K, int N)
{
    extern __shared__ char smg[];
    const uint32_t sbase = smem_u32(smg);
    const int tid  = threadIdx.x;
    const int lane = tid & 31, wid = tid >> 5;       // 16 warps
    const int m0 = blockIdx.y << 7, n0 = blockIdx.x << 7;
    const int wm = (wid & 3) << 5;                   // 0,32,64,96
    const int wn = (wid >> 2) << 5;                  // 0,32,64,96

    // ---- loader mapping: 8 threads cover one 128B row, 64 rows per pass ----
    const int lrow = tid >> 3;         // 0..63
    const int lkg  = tid & 7;          // 16B group within row
    const __nv_bfloat16* srcs[4];
    srcs[0] = Ah + (size_t)(m0 + lrow) * K + lkg * 8;
    srcs[1] = Al + (size_t)(m0 + lrow) * K + lkg * 8;
    srcs[2] = Bh + (size_t)(n0 + lrow) * K + lkg * 8;
    srcs[3] = Bl + (size_t)(n0 + lrow) * K + lkg * 8;
    uint32_t dbase[4];
    {
        uint32_t sw = swz(lrow * 128 + lkg * 16);
#pragma unroll
        for (int t = 0; t < 4; t++) dbase[t] = sbase + t * TB + sw;
    }

#define LOAD_STAGE(c, s) do {                                               \
    const size_t kb_ = (size_t)(c) << 6;                                    \
    const uint32_t so_ = (uint32_t)(s) * (4 * TB);                          \
    _Pragma("unroll")                                                       \
    for (int t_ = 0; t_ < 4; t_++) {                                        \
        const __nv_bfloat16* sp_ = srcs[t_] + kb_;                          \
        _Pragma("unroll")                                                   \
        for (int j_ = 0; j_ < 2; j_++)                                      \
            CP_ASYNC16(dbase[t_] + so_ + j_ * 8192, sp_ + (size_t)j_ * 64 * K); \
    }                                                                       \
} while (0)

    float acc[2][4][4];
#pragma unroll
    for (int mi = 0; mi < 2; mi++)
#pragma unroll
        for (int ni = 0; ni < 4; ni++)
#pragma unroll
            for (int e = 0; e < 4; e++) acc[mi][ni][e] = 0.f;

    const int nc = K >> 6;
    LOAD_STAGE(0, 0); CP_COMMIT();
    LOAD_STAGE(1, 1); CP_COMMIT();

    // Fragment addressing: row within tile steps by multiples of 16, so the
    // SW128 xor constant (row&7)<<4 is invariant per thread.
    const uint32_t arow = wm + (lane & 15);
    const uint32_t brow = wn + (lane & 15);
    const uint32_t axor = (arow & 7) << 4;
    const uint32_t bxor = (brow & 7) << 4;
    const uint32_t chalf = (lane >> 4) << 4;         // 0 or 16 within k-block

    for (int c = 0; c < nc; c++) {
        CP_WAIT1();
        __syncthreads();
        if (c + 2 < nc) LOAD_STAGE(c + 2, (c + 2) % 3);
        CP_COMMIT();

        const uint32_t st = (uint32_t)(c % 3) * (4 * TB);
        const uint32_t aAh = sbase + st + arow * 128;
        const uint32_t aAl = aAh + TB;
        const uint32_t aBh = sbase + st + 2 * TB + brow * 128;
        const uint32_t aBl = aBh + TB;

#pragma unroll
        for (int kk = 0; kk < 4; kk++) {
            const uint32_t ca = (kk * 32 + chalf) ^ axor;
            const uint32_t cb = (kk * 32 + chalf) ^ bxor;
            uint32_t ah[2][4], al[2][4], bh[4][2], bl[4][2];
#pragma unroll
            for (int mi = 0; mi < 2; mi++) {
                ldsm4(ah[mi], aAh + mi * (16 * 128) + ca);
                ldsm4(al[mi], aAl + mi * (16 * 128) + ca);
            }
#pragma unroll
            for (int nh = 0; nh < 2; nh++) {
                uint32_t r[4];
                ldsm4(r, aBh + nh * (16 * 128) + cb);
                bh[2*nh][0] = r[0]; bh[2*nh][1] = r[2];
                bh[2*nh+1][0] = r[1]; bh[2*nh+1][1] = r[3];
                ldsm4(r, aBl + nh * (16 * 128) + cb);
                bl[2*nh][0] = r[0]; bl[2*nh][1] = r[2];
                bl[2*nh+1][0] = r[1]; bl[2*nh+1][1] = r[3];
            }
            // term-major order: same-accumulator reuse distance = 8 MMAs
#pragma unroll
            for (int mi = 0; mi < 2; mi++)
#pragma unroll
                for (int ni = 0; ni < 4; ni++)
                    mma16816(acc[mi][ni], ah[mi], bh[ni]);
#pragma unroll
            for (int mi = 0; mi < 2; mi++)
#pragma unroll
                for (int ni = 0; ni < 4; ni++)
                    mma16816(acc[mi][ni], ah[mi], bl[ni]);
#pragma unroll
            for (int mi = 0; mi < 2; mi++)
#pragma unroll
                for (int ni = 0; ni < 4; ni++)
                    mma16816(acc[mi][ni], al[mi], bh[ni]);
        }
    }

    // ---- epilogue ----
    const int g = lane >> 2, tig = lane & 3;
    float2 bv[4];
#pragma unroll
    for (int ni = 0; ni < 4; ni++)
        bv[ni] = *(const float2*)(bias + n0 + wn + ni * 8 + tig * 2);

#pragma unroll
    for (int mi = 0; mi < 2; mi++) {
        const int r1 = m0 + wm + mi * 16 + g;
        const int r2 = r1 + 8;
#pragma unroll
        for (int ni = 0; ni < 4; ni++) {
            const int col = n0 + wn + ni * 8 + tig * 2;
            float2 v0 = make_float2(acc[mi][ni][0] + bv[ni].x, acc[mi][ni][1] + bv[ni].y);
            float2 v1 = make_float2(acc[mi][ni][2] + bv[ni].x, acc[mi][ni][3] + bv[ni].y);
            if (EPI == EPI_RELU) {
                // relu + direct split-bf16 store (hi/lo)
                v0.x = fmaxf(v0.x, 0.f); v0.y = fmaxf(v0.y, 0.f);
                v1.x = fmaxf(v1.x, 0.f); v1.y = fmaxf(v1.y, 0.f);
                uint32_t H, L;
                split2(v0.x, v0.y, H, L);
                *(uint32_t*)(Ch + (size_t)r1 * N + col) = H;
                *(uint32_t*)(Cl + (size_t)r1 * N + col) = L;
                split2(v1.x, v1.y, H, L);
                *(uint32_t*)(Ch + (size_t)r2 * N + col) = H;
                *(uint32_t*)(Cl + (size_t)r2 * N + col) = L;
            } else {
                if (EPI == EPI_RES) {
                    float2 q0 = *(const float2*)(Res + (size_t)r1 * N + col);
                    float2 q1 = *(const float2*)(Res + (size_t)r2 * N + col);
                    v0.x += q0.x; v0.y += q0.y; v1.x += q1.x; v1.y += q1.y;
                }
                *(float2*)(C + (size_t)r1 * N + col) = v0;
                *(float2*)(C + (size_t)r2 * N + col) = v1;
            }
        }
    }
#undef LOAD_STAGE
}

// ---------------------------------------------------------------------------
// Block-causal flash attention (fp32). BLK=64 == tile size.
// Writes output directly as split bf16 (hi/lo).
// ---------------------------------------------------------------------------
#define AST 68
#define ATTN_SMEM (3 * 64 * AST * 4)

__global__ __launch_bounds__(256)
void attn_kernel(const float* __restrict__ qkv,
                 __nv_bfloat16* __restrict__ oh, __nv_bfloat16* __restrict__ ol)
{
    extern __shared__ float sm[];
    float* Qs = sm;
    float* Ks = sm + 64 * AST;
    float* Vs = sm + 2 * 64 * AST;

    const int jq   = blockIdx.x;
    const int b    = blockIdx.y >> 4;
    const int h    = blockIdx.y & 15;
    const int tid  = threadIdx.x;
    const int lane = tid & 31;
    const int warp = tid >> 5;
    const int r0   = warp << 3;

    const float* qbase = qkv + ((size_t)b * SS + (size_t)jq * 64) * 3072 + h * 64;
    const float* kbase = qkv + (size_t)b * SS * 3072 + 1024 + h * 64;
    const float* vbase = kbase + 1024;

    for (int f = tid; f < 1024; f += 256) {
        int r = f >> 4, c4 = (f & 15) << 2;
        float4 v = *(const float4*)(qbase + (size_t)r * 3072 + c4);
        float* q = &Qs[r * AST + c4];
        q[0] = v.x * 0.125f; q[1] = v.y * 0.125f; q[2] = v.z * 0.125f; q[3] = v.w * 0.125f;
    }

    float O0[8], O1[8], mr[8], lr[8];
#pragma unroll
    for (int i = 0; i < 8; i++) { O0[i] = 0.f; O1[i] = 0.f; mr[i] = -INFINITY; lr[i] = 0.f; }

    for (int kb = 0; kb <= jq; kb++) {
        __syncthreads();
        for (int f = tid; f < 1024; f += 256) {
            int r = f >> 4, c4 = (f & 15) << 2;
            size_t roff = (size_t)(kb * 64 + r) * 3072 + c4;
            float4 kv = *(const float4*)(kbase + roff);
            float4 vv = *(const float4*)(vbase + roff);
            float* kp = &Ks[r * AST + c4];
            float* vp = &Vs[r * AST + c4];
            kp[0] = kv.x; kp[1] = kv.y; kp[2] = kv.z; kp[3] = kv.w;
            vp[0] = vv.x; vp[1] = vv.y; vp[2] = vv.z; vp[3] = vv.w;
        }
        __syncthreads();

        float sc0[8], sc1[8];
#pragma unroll
        for (int i = 0; i < 8; i++) { sc0[i] = 0.f; sc1[i] = 0.f; }
        const float* kr0 = &Ks[(2 * lane) * AST];
        const float* kr1 = kr0 + AST;
#pragma unroll
        for (int d4 = 0; d4 < 64; d4 += 4) {
            float4 k0 = *(const float4*)(kr0 + d4);
            float4 k1 = *(const float4*)(kr1 + d4);
#pragma unroll
            for (int i = 0; i < 8; i++) {
                float4 q = *(const float4*)&Qs[(r0 + i) * AST + d4];
                sc0[i] += q.x * k0.x + q.y * k0.y + q.z * k0.z + q.w * k0.w;
                sc1[i] += q.x * k1.x + q.y * k1.y + q.z * k1.z + q.w * k1.w;
            }
        }
        __syncthreads();

#pragma unroll
        for (int i = 0; i < 8; i++) {
            float mb = fmaxf(sc0[i], sc1[i]);
#pragma unroll
            for (int off = 16; off; off >>= 1) mb = fmaxf(mb, __shfl_xor_sync(0xffffffffu, mb, off));
            float mnew  = fmaxf(mr[i], mb);
            float alpha = __expf(mr[i] - mnew);
            float p0 = __expf(sc0[i] - mnew);
            float p1 = __expf(sc1[i] - mnew);
            float s  = p0 + p1;
#pragma unroll
            for (int off = 16; off; off >>= 1) s += __shfl_xor_sync(0xffffffffu, s, off);
            lr[i] = lr[i] * alpha + s;
            mr[i] = mnew;
            O0[i] *= alpha; O1[i] *= alpha;
            Ks[(r0 + i) * AST + 2 * lane]     = p0;
            Ks[(r0 + i) * AST + 2 * lane + 1] = p1;
        }
        __syncwarp();

#pragma unroll 4
        for (int kc = 0; kc < 64; kc++) {
            float2 v = *(const float2*)&Vs[kc * AST + 2 * lane];
#pragma unroll
            for (int i = 0; i < 8; i++) {
                float p = Ks[(r0 + i) * AST + kc];
                O0[i] += p * v.x;
                O1[i] += p * v.y;
            }
        }
    }

    const size_t obase = ((size_t)b * SS + (size_t)jq * 64) * DD + h * 64 + 2 * lane;
#pragma unroll
    for (int i = 0; i < 8; i++) {
        float inv = 1.0f / lr[i];
        uint32_t H, L;
        split2(O0[i] * inv, O1[i] * inv, H, L);
        *(uint32_t*)(oh + obase + (size_t)(r0 + i) * DD) = H;
        *(uint32_t*)(ol + obase + (size_t)(r0 + i) * DD) = L;
    }
}

// ---------------------------------------------------------------------------
// LayerNorm over D=1024, one block (256 threads) per row.
// Writes fp32 out + split bf16 (hi/lo).
// ---------------------------------------------------------------------------
__global__ __launch_bounds__(256)
void ln_kernel(const float* __restrict__ in, const float* __restrict__ w,
               const float* __restrict__ b, float* __restrict__ out,
               __nv_bfloat16* __restrict__ oh, __nv_bfloat16* __restrict__ ol)
{
    __shared__ float s_sum[8], s_sq[8], s_bc[2];
    const int row = blockIdx.x, tid = threadIdx.x;
    float4 v = ((const float4*)(in + (size_t)row * 1024))[tid];
    float s = v.x + v.y + v.z + v.w;
    float q = v.x * v.x + v.y * v.y + v.z * v.z + v.w * v.w;
#pragma unroll
    for (int o = 16; o; o >>= 1) {
        s += __shfl_xor_sync(0xffffffffu, s, o);
        q += __shfl_xor_sync(0xffffffffu, q, o);
    }
    if ((tid & 31) == 0) { s_sum[tid >> 5] = s; s_sq[tid >> 5] = q; }
    __syncthreads();
    if (tid == 0) {
        float ts = 0.f, tq = 0.f;
#pragma unroll
        for (int i = 0; i < 8; i++) { ts += s_sum[i]; tq += s_sq[i]; }
        float mu  = ts * (1.f / 1024.f);
        float var = tq * (1.f / 1024.f) - mu * mu;
        s_bc[0] = mu;
        s_bc[1] = rsqrtf(var + 1e-5f);
    }
    __syncthreads();
    float mu = s_bc[0], rs = s_bc[1];
    float4 wv = ((const float4*)w)[tid];
    float4 bv = ((const float4*)b)[tid];
    float4 ov;
    ov.x = (v.x - mu) * rs * wv.x + bv.x;
    ov.y = (v.y - mu) * rs * wv.y + bv.y;
    ov.z = (v.z - mu) * rs * wv.z + bv.z;
    ov.w = (v.w - mu) * rs * wv.w + bv.w;
    ((float4*)(out + (size_t)row * 1024))[tid] = ov;
    uint2 H, L;
    split2(ov.x, ov.y, H.x, L.x);
    split2(ov.z, ov.w, H.y, L.y);
    ((uint2*)(oh + (size_t)row * 1024))[tid] = H;
    ((uint2*)(ol + (size_t)row * 1024))[tid] = L;
}

// initial copy: x -> working fp32 buffer + split bf16
__global__ __launch_bounds__(256)
void init_kernel(const float4* __restrict__ s, float4* __restrict__ d,
                 uint2* __restrict__ hi, uint2* __restrict__ lo)
{
    int i = blockIdx.x * 256 + threadIdx.x;
    float4 v = s[i];
    d[i] = v;
    uint2 H, L;
    split2(v.x, v.y, H.x, L.x);
    split2(v.z, v.w, H.y, L.y);
    hi[i] = H;
    lo[i] = L;
}

// ---------------------------------------------------------------------------
// Host orchestration (graph-capturable: kernel launches only)
// ---------------------------------------------------------------------------
extern "C" void kernel_launch(void* const* d_in, const int* in_sizes, int n_in,
                              void* d_out, int out_size)
{
    (void)in_sizes; (void)n_in; (void)out_size;
    const float* x_in = (const float*)d_in[0];
    const float* ipw  = (const float*)d_in[1];   // [L,3072,1024]
    const float* ipb  = (const float*)d_in[2];   // [L,3072]
    const float* ow   = (const float*)d_in[3];   // [L,1024,1024]
    const float* ob   = (const float*)d_in[4];   // [L,1024]
    const float* n1w  = (const float*)d_in[5];
    const float* n1b  = (const float*)d_in[6];
    const float* f1w  = (const float*)d_in[7];   // [L,4096,1024]
    const float* f1b  = (const float*)d_in[8];   // [L,4096]
    const float* f2w  = (const float*)d_in[9];   // [L,1024,4096]
    const float* f2b  = (const float*)d_in[10];  // [L,1024]
    const float* n2w  = (const float*)d_in[11];
    const float* n2b  = (const float*)d_in[12];
    float* out = (float*)d_out;

    float *px, *pqkv, *ptmp;
    __nv_bfloat16 *pxh, *pxl, *poh, *pol, *pah, *pal, *pwh, *pwl;
    cudaGetSymbolAddress((void**)&px,   g_x);
    cudaGetSymbolAddress((void**)&pqkv, g_qkv);
    cudaGetSymbolAddress((void**)&ptmp, g_tmp);
    cudaGetSymbolAddress((void**)&pxh,  g_xh);
    cudaGetSymbolAddress((void**)&pxl,  g_xl);
    cudaGetSymbolAddress((void**)&poh,  g_oh);
    cudaGetSymbolAddress((void**)&pol,  g_ol);
    cudaGetSymbolAddress((void**)&pah,  g_ah);
    cudaGetSymbolAddress((void**)&pal,  g_al);
    cudaGetSymbolAddress((void**)&pwh,  g_wh);
    cudaGetSymbolAddress((void**)&pwl,  g_wl);

    cudaFuncSetAttribute((const void*)attn_kernel,
                         cudaFuncAttributeMaxDynamicSharedMemorySize, ATTN_SMEM);
    cudaFuncSetAttribute((const void*)gemm_tc<EPI_BIAS>,
                         cudaFuncAttributeMaxDynamicSharedMemorySize, GEMM_SMEM);
    cudaFuncSetAttribute((const void*)gemm_tc<EPI_RELU>,
                         cudaFuncAttributeMaxDynamicSharedMemorySize, GEMM_SMEM);
    cudaFuncSetAttribute((const void*)gemm_tc<EPI_RES>,
                         cudaFuncAttributeMaxDynamicSharedMemorySize, GEMM_SMEM);

#define SPLIT(src, hi, lo, nelem) \
    split_kernel<<<((nelem)/4 + 255)/256, 256>>>((const float4*)(src), (uint2*)(hi), (uint2*)(lo), (nelem)/4)

    // x -> working buffer + initial split
    init_kernel<<<4096, 256>>>((const float4*)x_in, (float4*)px, (uint2*)pxh, (uint2*)pxl);

    for (int l = 0; l < NLAYERS; l++) {
        const float* Wqkv = ipw + (size_t)l * 3 * DD * DD;
        const float* Bqkv = ipb + (size_t)l * 3 * DD;
        const float* Wout = ow  + (size_t)l * DD * DD;
        const float* Bout = ob  + (size_t)l * DD;
        const float* W1   = f1w + (size_t)l * DFF * DD;
        const float* B1   = f1b + (size_t)l * DFF;
        const float* W2   = f2w + (size_t)l * DD * DFF;
        const float* B2   = f2b + (size_t)l * DD;

        // qkv = x @ Wqkv^T + b
        SPLIT(Wqkv, pwh, pwl, 3 * DD * DD);
        gemm_tc<EPI_BIAS><<<dim3(24, 32), 512, GEMM_SMEM>>>(
            pxh, pxl, pwh, pwl, Bqkv, nullptr, pqkv, nullptr, nullptr, DD, 3 * DD);

        // block-causal attention -> split o
        attn_kernel<<<dim3(SS / 64, BB * HH), 256, ATTN_SMEM>>>(pqkv, poh, pol);

        // tmp = x + o @ Wout^T + b
        SPLIT(Wout, pwh, pwl, DD * DD);
        gemm_tc<EPI_RES><<<dim3(8, 32), 512, GEMM_SMEM>>>(
            poh, pol, pwh, pwl, Bout, px, ptmp, nullptr, nullptr, DD, DD);
        // x = LN1(tmp) (+ split)
        ln_kernel<<<MM, 256>>>(ptmp, n1w + (size_t)l * DD, n1b + (size_t)l * DD,
                               px, pxh, pxl);

        // h = relu(x @ W1^T + b1) -> split h directly
        SPLIT(W1, pwh, pwl, DFF * DD);
        gemm_tc<EPI_RELU><<<dim3(32, 32), 512, GEMM_SMEM>>>(
            pxh, pxl, pwh, pwl, B1, nullptr, nullptr, pah, pal, DD, DFF);

        // tmp = x + h @ W2^T + b2
        SPLIT(W2, pwh, pwl, DD * DFF);
        gemm_tc<EPI_RES><<<dim3(8, 32), 512, GEMM_SMEM>>>(
            pah, pal, pwh, pwl, B2, px, ptmp, nullptr, nullptr, DFF, DD);
        // x = LN2(tmp) (last layer writes final output; split kept for uniformity)
        ln_kernel<<<MM, 256>>>(ptmp, n2w + (size_t)l * DD, n2b + (size_t)l * DD,
                               (l == NLAYERS - 1) ? out : px, pxh, pxl);
    }
#undef SPLIT
}

// round 14
// speedup vs baseline: 2.4999x; 1.2525x over previous
#include <cuda_runtime.h>
#include <cuda_bf16.h>
#include <math.h>
#include <stdint.h>

// Problem constants
#define BB 4
#define SS 1024
#define DD 1024
#define HH 16
#define DFF 4096
#define NLAYERS 4
#define MM (BB*SS)          // 4096 rows

// ---------------------------------------------------------------------------
// Scratch (static device globals -- no allocation allowed)
// ---------------------------------------------------------------------------
__device__ float g_x  [(size_t)MM * DD];        // activations (fp32, residual)
__device__ float g_tmp[(size_t)MM * DD];        // pre-LN buffer
// split-bf16 activation buffers
__device__ __nv_bfloat16 g_qkvh[(size_t)MM * 3 * DD];     // qkv hi (Q pre-scaled)
__device__ __nv_bfloat16 g_qkvl[(size_t)MM * 3 * DD];     // qkv lo
__device__ __nv_bfloat16 g_xh[(size_t)MM * DD];           // x hi (LN output)
__device__ __nv_bfloat16 g_xl[(size_t)MM * DD];           // x lo
__device__ __nv_bfloat16 g_oh[(size_t)MM * DD];           // attn-out hi
__device__ __nv_bfloat16 g_ol[(size_t)MM * DD];           // attn-out lo
__device__ __nv_bfloat16 g_ah[(size_t)MM * DFF];          // FF hidden hi
__device__ __nv_bfloat16 g_al[(size_t)MM * DFF];          // FF hidden lo
__device__ __nv_bfloat16 g_wh[(size_t)4 * 1024 * 1024];   // W hi
__device__ __nv_bfloat16 g_wl[(size_t)4 * 1024 * 1024];   // W lo

// ---------------------------------------------------------------------------
// Helpers
// ---------------------------------------------------------------------------
__device__ __forceinline__ uint32_t smem_u32(const void* p) {
    uint32_t a;
    asm("{ .reg .u64 t; cvta.to.shared.u64 t, %1; cvt.u32.u64 %0, t; }"
        : "=r"(a) : "l"(p));
    return a;
}
__device__ __forceinline__ uint32_t swz(uint32_t off) {
    return off ^ ((off >> 3) & 0x70);
}
// pack two floats into bf16x2 (hi) and residual bf16x2 (lo)
__device__ __forceinline__ void split2(float x, float y, uint32_t& H, uint32_t& L) {
    __nv_bfloat162 h = __floats2bfloat162_rn(x, y);
    __nv_bfloat162 l = __floats2bfloat162_rn(x - __low2float(h), y - __high2float(h));
    H = *(uint32_t*)&h;
    L = *(uint32_t*)&l;
}

#define CP_ASYNC16(dst, src) \
    asm volatile("cp.async.cg.shared.global [%0], [%1], 16;" :: "r"(dst), "l"(src))
#define CP_COMMIT() asm volatile("cp.async.commit_group;")
#define CP_WAIT1()  asm volatile("cp.async.wait_group 1;")
#define CP_WAIT0()  asm volatile("cp.async.wait_group 0;")

__device__ __forceinline__ void ldsm4(uint32_t* r, uint32_t addr) {
    asm volatile("ldmatrix.sync.aligned.m8n8.x4.shared.b16 {%0,%1,%2,%3}, [%4];"
        : "=r"(r[0]), "=r"(r[1]), "=r"(r[2]), "=r"(r[3]) : "r"(addr));
}
__device__ __forceinline__ void ldsm4t(uint32_t* r, uint32_t addr) {
    asm volatile("ldmatrix.sync.aligned.m8n8.x4.trans.shared.b16 {%0,%1,%2,%3}, [%4];"
        : "=r"(r[0]), "=r"(r[1]), "=r"(r[2]), "=r"(r[3]) : "r"(addr));
}
__device__ __forceinline__ void mma16816(float* d, const uint32_t* a, const uint32_t* b) {
    asm volatile(
        "mma.sync.aligned.m16n8k16.row.col.f32.bf16.bf16.f32 "
        "{%0,%1,%2,%3}, {%4,%5,%6,%7}, {%8,%9}, {%0,%1,%2,%3};"
        : "+f"(d[0]), "+f"(d[1]), "+f"(d[2]), "+f"(d[3])
        : "r"(a[0]), "r"(a[1]), "r"(a[2]), "r"(a[3]), "r"(b[0]), "r"(b[1]));
}

// ---------------------------------------------------------------------------
// fp32 -> (hi, lo) bf16 split (weights only)
// ---------------------------------------------------------------------------
__global__ __launch_bounds__(256)
void split_kernel(const float4* __restrict__ in, uint2* __restrict__ hi,
                  uint2* __restrict__ lo, int n4)
{
    int i = blockIdx.x * 256 + threadIdx.x;
    if (i >= n4) return;
    float4 v = in[i];
    uint2 H, L;
    split2(v.x, v.y, H.x, L.x);
    split2(v.z, v.w, H.y, L.y);
    hi[i] = H;
    lo[i] = L;
}

// ---------------------------------------------------------------------------
// Tensor-core split-bf16 GEMM: C[M,N] = A[M,K] @ B[N,K]^T
// CTA: 128x128 tile, BK=64, 16 warps (warp tile 32x32), 3-stage cp.async.
// EPI_BIAS: fp32 C.  EPI_RES: fp32 C + residual.
// EPI_RELU: relu -> split bf16.  EPI_QKV: split bf16, Q cols scaled by 0.125.
// ---------------------------------------------------------------------------
enum { EPI_BIAS = 0, EPI_RELU = 1, EPI_RES = 2, EPI_QKV = 3 };

#define TB 16384                       // one 128x64 bf16 tile
#define GEMM_SMEM (3 * 4 * TB)         // 196608 B

template<int EPI>
__global__ __launch_bounds__(512, 1)
void gemm_tc(const __nv_bfloat16* __restrict__ Ah, const __nv_bfloat16* __restrict__ Al,
             const __nv_bfloat16* __restrict__ Bh, const __nv_bfloat16* __restrict__ Bl,
             const float* __restrict__ bias, const float* __restrict__ Res,
             float* __restrict__ C,
             __nv_bfloat16* __restrict__ Ch, __nv_bfloat16* __restrict__ Cl,
             int K, int N)
{
    extern __shared__ char smg[];
    const uint32_t sbase = smem_u32(smg);
    const int tid  = threadIdx.x;
    const int lane = tid & 31, wid = tid >> 5;       // 16 warps
    const int m0 = blockIdx.y << 7, n0 = blockIdx.x << 7;
    const int wm = (wid & 3) << 5;                   // 0,32,64,96
    const int wn = (wid >> 2) << 5;                  // 0,32,64,96

    const int lrow = tid >> 3;         // 0..63
    const int lkg  = tid & 7;          // 16B group within row
    const __nv_bfloat16* srcs[4];
    srcs[0] = Ah + (size_t)(m0 + lrow) * K + lkg * 8;
    srcs[1] = Al + (size_t)(m0 + lrow) * K + lkg * 8;
    srcs[2] = Bh + (size_t)(n0 + lrow) * K + lkg * 8;
    srcs[3] = Bl + (size_t)(n0 + lrow) * K + lkg * 8;
    uint32_t dbase[4];
    {
        uint32_t sw = swz(lrow * 128 + lkg * 16);
#pragma unroll
        for (int t = 0; t < 4; t++) dbase[t] = sbase + t * TB + sw;
    }

#define LOAD_STAGE(c, s) do {                                               \
    const size_t kb_ = (size_t)(c) << 6;                                    \
    const uint32_t so_ = (uint32_t)(s) * (4 * TB);                          \
    _Pragma("unroll")                                                       \
    for (int t_ = 0; t_ < 4; t_++) {                                        \
        const __nv_bfloat16* sp_ = srcs[t_] + kb_;                          \
        _Pragma("unroll")                                                   \
        for (int j_ = 0; j_ < 2; j_++)                                      \
            CP_ASYNC16(dbase[t_] + so_ + j_ * 8192, sp_ + (size_t)j_ * 64 * K); \
    }                                                                       \
} while (0)

    float acc[2][4][4];
#pragma unroll
    for (int mi = 0; mi < 2; mi++)
#pragma unroll
        for (int ni = 0; ni < 4; ni++)
#pragma unroll
            for (int e = 0; e < 4; e++) acc[mi][ni][e] = 0.f;

    const int nc = K >> 6;
    LOAD_STAGE(0, 0); CP_COMMIT();
    LOAD_STAGE(1, 1); CP_COMMIT();

    const uint32_t arow = wm + (lane & 15);
    const uint32_t brow = wn + (lane & 15);
    const uint32_t axor = (arow & 7) << 4;
    const uint32_t bxor = (brow & 7) << 4;
    const uint32_t chalf = (lane >> 4) << 4;

    for (int c = 0; c < nc; c++) {
        CP_WAIT1();
        __syncthreads();
        if (c + 2 < nc) LOAD_STAGE(c + 2, (c + 2) % 3);
        CP_COMMIT();

        const uint32_t st = (uint32_t)(c % 3) * (4 * TB);
        const uint32_t aAh = sbase + st + arow * 128;
        const uint32_t aAl = aAh + TB;
        const uint32_t aBh = sbase + st + 2 * TB + brow * 128;
        const uint32_t aBl = aBh + TB;

#pragma unroll
        for (int kk = 0; kk < 4; kk++) {
            const uint32_t ca = (kk * 32 + chalf) ^ axor;
            const uint32_t cb = (kk * 32 + chalf) ^ bxor;
            uint32_t ah[2][4], al[2][4], bh[4][2], bl[4][2];
#pragma unroll
            for (int mi = 0; mi < 2; mi++) {
                ldsm4(ah[mi], aAh + mi * (16 * 128) + ca);
                ldsm4(al[mi], aAl + mi * (16 * 128) + ca);
            }
#pragma unroll
            for (int nh = 0; nh < 2; nh++) {
                uint32_t r[4];
                ldsm4(r, aBh + nh * (16 * 128) + cb);
                bh[2*nh][0] = r[0]; bh[2*nh][1] = r[2];
                bh[2*nh+1][0] = r[1]; bh[2*nh+1][1] = r[3];
                ldsm4(r, aBl + nh * (16 * 128) + cb);
                bl[2*nh][0] = r[0]; bl[2*nh][1] = r[2];
                bl[2*nh+1][0] = r[1]; bl[2*nh+1][1] = r[3];
            }
#pragma unroll
            for (int mi = 0; mi < 2; mi++)
#pragma unroll
                for (int ni = 0; ni < 4; ni++)
                    mma16816(acc[mi][ni], ah[mi], bh[ni]);
#pragma unroll
            for (int mi = 0; mi < 2; mi++)
#pragma unroll
                for (int ni = 0; ni < 4; ni++)
                    mma16816(acc[mi][ni], ah[mi], bl[ni]);
#pragma unroll
            for (int mi = 0; mi < 2; mi++)
#pragma unroll
                for (int ni = 0; ni < 4; ni++)
                    mma16816(acc[mi][ni], al[mi], bh[ni]);
        }
    }

    // ---- epilogue ----
    const int g = lane >> 2, tig = lane & 3;
    float2 bv[4];
#pragma unroll
    for (int ni = 0; ni < 4; ni++)
        bv[ni] = *(const float2*)(bias + n0 + wn + ni * 8 + tig * 2);

#pragma unroll
    for (int mi = 0; mi < 2; mi++) {
        const int r1 = m0 + wm + mi * 16 + g;
        const int r2 = r1 + 8;
#pragma unroll
        for (int ni = 0; ni < 4; ni++) {
            const int col = n0 + wn + ni * 8 + tig * 2;
            float2 v0 = make_float2(acc[mi][ni][0] + bv[ni].x, acc[mi][ni][1] + bv[ni].y);
            float2 v1 = make_float2(acc[mi][ni][2] + bv[ni].x, acc[mi][ni][3] + bv[ni].y);
            if (EPI == EPI_RELU) {
                v0.x = fmaxf(v0.x, 0.f); v0.y = fmaxf(v0.y, 0.f);
                v1.x = fmaxf(v1.x, 0.f); v1.y = fmaxf(v1.y, 0.f);
                uint32_t H, L;
                split2(v0.x, v0.y, H, L);
                *(uint32_t*)(Ch + (size_t)r1 * N + col) = H;
                *(uint32_t*)(Cl + (size_t)r1 * N + col) = L;
                split2(v1.x, v1.y, H, L);
                *(uint32_t*)(Ch + (size_t)r2 * N + col) = H;
                *(uint32_t*)(Cl + (size_t)r2 * N + col) = L;
            } else if (EPI == EPI_QKV) {
                // scale Q columns by 0.125 (exact power of two; commutes with split)
                const float s = (col < 1024) ? 0.125f : 1.0f;
                uint32_t H, L;
                split2(v0.x * s, v0.y * s, H, L);
                *(uint32_t*)(Ch + (size_t)r1 * N + col) = H;
                *(uint32_t*)(Cl + (size_t)r1 * N + col) = L;
                split2(v1.x * s, v1.y * s, H, L);
                *(uint32_t*)(Ch + (size_t)r2 * N + col) = H;
                *(uint32_t*)(Cl + (size_t)r2 * N + col) = L;
            } else {
                if (EPI == EPI_RES) {
                    float2 q0 = *(const float2*)(Res + (size_t)r1 * N + col);
                    float2 q1 = *(const float2*)(Res + (size_t)r2 * N + col);
                    v0.x += q0.x; v0.y += q0.y; v1.x += q1.x; v1.y += q1.y;
                }
                *(float2*)(C + (size_t)r1 * N + col) = v0;
                *(float2*)(C + (size_t)r2 * N + col) = v1;
            }
        }
    }
#undef LOAD_STAGE
}

// ---------------------------------------------------------------------------
// Tensor-core block-causal flash attention (split bf16, mma.m16n8k16).
// CTA = 128 threads (4 warps), one 64-row q-block for one (b,h).
// Warp w owns query rows 16w..16w+15 (all 64 cols): softmax reductions are
// intra-quad shfl only. P lives in registers (S-acc layout == A-frag layout).
// smem: Qh Ql Kh Kl Vh Vl tiles, 64x64 bf16 each (8192 B) = 48 KB.
// ---------------------------------------------------------------------------
#define ATTN_SMEM 49152

__global__ __launch_bounds__(128, 4)
void attn_tc(const __nv_bfloat16* __restrict__ qvh, const __nv_bfloat16* __restrict__ qvl,
             __nv_bfloat16* __restrict__ oh, __nv_bfloat16* __restrict__ ol)
{
    extern __shared__ char smx[];
    const uint32_t sb  = smem_u32(smx);
    const uint32_t sQh = sb, sQl = sb + 8192;
    const uint32_t sKh = sb + 16384, sKl = sb + 24576;
    const uint32_t sVh = sb + 32768, sVl = sb + 40960;

    const int jq = blockIdx.x;
    const int b  = blockIdx.y >> 4, h = blockIdx.y & 15;
    const int tid = threadIdx.x, lane = tid & 31, w = tid >> 5;
    const int g = lane >> 2, tig = lane & 3;

    // loader: 8 threads per 128B row, 16 rows per pass, 4 passes per tile
    const int lrow = tid >> 3;                 // 0..15
    const uint32_t ld_sw = swz(lrow * 128 + (tid & 7) * 16);
    const size_t qtok = (size_t)(b * SS + jq * 64 + lrow) * 3072 + h * 64 + (tid & 7) * 8;
    const size_t ktokb = (size_t)(b * SS + lrow) * 3072 + 1024 + h * 64 + (tid & 7) * 8;

    // Q + K/V(0) loads
#pragma unroll
    for (int p = 0; p < 4; p++) {
        CP_ASYNC16(sQh + ld_sw + p * 2048, qvh + qtok + (size_t)p * 16 * 3072);
        CP_ASYNC16(sQl + ld_sw + p * 2048, qvl + qtok + (size_t)p * 16 * 3072);
    }
#pragma unroll
    for (int p = 0; p < 4; p++) {
        const size_t t = ktokb + (size_t)p * 16 * 3072;
        CP_ASYNC16(sKh + ld_sw + p * 2048, qvh + t);
        CP_ASYNC16(sKl + ld_sw + p * 2048, qvl + t);
        CP_ASYNC16(sVh + ld_sw + p * 2048, qvh + t + 1024);
        CP_ASYNC16(sVl + ld_sw + p * 2048, qvl + t + 1024);
    }
    CP_COMMIT();

    float accO[8][4];
#pragma unroll
    for (int ni = 0; ni < 8; ni++)
#pragma unroll
        for (int e = 0; e < 4; e++) accO[ni][e] = 0.f;
    float mrow[2] = {-INFINITY, -INFINITY};
    float lsum[2] = {0.f, 0.f};

    const uint32_t arow  = 16 * w + (lane & 15);
    const uint32_t krow  = (lane & 15);
    const uint32_t sxor  = (lane & 7) << 4;
    const uint32_t chalf = (lane >> 4) << 4;
    const uint32_t aQh = sQh + arow * 128, aQl = sQl + arow * 128;

    for (int kb = 0; kb <= jq; kb++) {
        CP_WAIT0();
        __syncthreads();

        // ---- S = Q K^T (3-term split) ----
        float accS[8][4];
#pragma unroll
        for (int ni = 0; ni < 8; ni++)
#pragma unroll
            for (int e = 0; e < 4; e++) accS[ni][e] = 0.f;

#pragma unroll
        for (int ks = 0; ks < 4; ks++) {
            const uint32_t cc = (ks * 32 + chalf) ^ sxor;
            uint32_t qah[4], qal[4];
            ldsm4(qah, aQh + cc);
            ldsm4(qal, aQl + cc);
            uint32_t kbh[8][2], kbl[8][2];
#pragma unroll
            for (int kn = 0; kn < 4; kn++) {
                uint32_t r[4];
                ldsm4(r, sKh + (kn * 16 + krow) * 128 + cc);
                kbh[2*kn][0] = r[0]; kbh[2*kn][1] = r[2];
                kbh[2*kn+1][0] = r[1]; kbh[2*kn+1][1] = r[3];
                ldsm4(r, sKl + (kn * 16 + krow) * 128 + cc);
                kbl[2*kn][0] = r[0]; kbl[2*kn][1] = r[2];
                kbl[2*kn+1][0] = r[1]; kbl[2*kn+1][1] = r[3];
            }
#pragma unroll
            for (int ni = 0; ni < 8; ni++) mma16816(accS[ni], qah, kbh[ni]);
#pragma unroll
            for (int ni = 0; ni < 8; ni++) mma16816(accS[ni], qah, kbl[ni]);
#pragma unroll
            for (int ni = 0; ni < 8; ni++) mma16816(accS[ni], qal, kbh[ni]);
        }
        __syncthreads();              // all warps done reading K tile

        // prefetch K(kb+1) while softmax runs
        if (kb < jq) {
            const size_t tn = ktokb + (size_t)(kb + 1) * 64 * 3072;
#pragma unroll
            for (int p = 0; p < 4; p++) {
                CP_ASYNC16(sKh + ld_sw + p * 2048, qvh + tn + (size_t)p * 16 * 3072);
                CP_ASYNC16(sKl + ld_sw + p * 2048, qvl + tn + (size_t)p * 16 * 3072);
            }
            CP_COMMIT();
        }

        // ---- online softmax (registers only) ----
#pragma unroll
        for (int e = 0; e < 2; e++) {
            float mb = accS[0][2*e];
#pragma unroll
            for (int ni = 0; ni < 8; ni++) {
                mb = fmaxf(mb, accS[ni][2*e]);
                mb = fmaxf(mb, accS[ni][2*e+1]);
            }
            mb = fmaxf(mb, __shfl_xor_sync(0xffffffffu, mb, 1));
            mb = fmaxf(mb, __shfl_xor_sync(0xffffffffu, mb, 2));
            const float mnew = fmaxf(mrow[e], mb);
            const float alpha = __expf(mrow[e] - mnew);
            float rs = 0.f;
#pragma unroll
            for (int ni = 0; ni < 8; ni++) {
                float p0 = __expf(accS[ni][2*e]   - mnew);
                float p1 = __expf(accS[ni][2*e+1] - mnew);
                accS[ni][2*e] = p0; accS[ni][2*e+1] = p1;
                rs += p0 + p1;
            }
            rs += __shfl_xor_sync(0xffffffffu, rs, 1);
            rs += __shfl_xor_sync(0xffffffffu, rs, 2);
            lsum[e] = lsum[e] * alpha + rs;
            mrow[e] = mnew;
#pragma unroll
            for (int ni = 0; ni < 8; ni++) {
                accO[ni][2*e]   *= alpha;
                accO[ni][2*e+1] *= alpha;
            }
        }

        // ---- O += P V (3-term split; V^T frags via trans ldmatrix) ----
#pragma unroll
        for (int j = 0; j < 4; j++) {          // key k-steps
            uint32_t ph[4], pl[4];
            split2(accS[2*j][0],   accS[2*j][1],   ph[0], pl[0]);
            split2(accS[2*j][2],   accS[2*j][3],   ph[1], pl[1]);
            split2(accS[2*j+1][0], accS[2*j+1][1], ph[2], pl[2]);
            split2(accS[2*j+1][2], accS[2*j+1][3], ph[3], pl[3]);
            const uint32_t vbase = (j * 16 + krow) * 128;
            uint32_t bvh[8][2], bvl[8][2];
#pragma unroll
            for (int ng = 0; ng < 4; ng++) {
                const uint32_t cc = (ng * 32 + chalf) ^ sxor;
                uint32_t r[4];
                ldsm4t(r, sVh + vbase + cc);
                bvh[2*ng][0] = r[0]; bvh[2*ng][1] = r[1];
                bvh[2*ng+1][0] = r[2]; bvh[2*ng+1][1] = r[3];
                ldsm4t(r, sVl + vbase + cc);
                bvl[2*ng][0] = r[0]; bvl[2*ng][1] = r[1];
                bvl[2*ng+1][0] = r[2]; bvl[2*ng+1][1] = r[3];
            }
#pragma unroll
            for (int ni = 0; ni < 8; ni++) mma16816(accO[ni], ph, bvh[ni]);
#pragma unroll
            for (int ni = 0; ni < 8; ni++) mma16816(accO[ni], ph, bvl[ni]);
#pragma unroll
            for (int ni = 0; ni < 8; ni++) mma16816(accO[ni], pl, bvh[ni]);
        }
        __syncthreads();              // all warps done reading V tile

        // prefetch V(kb+1)
        if (kb < jq) {
            const size_t tn = ktokb + (size_t)(kb + 1) * 64 * 3072 + 1024;
#pragma unroll
            for (int p = 0; p < 4; p++) {
                CP_ASYNC16(sVh + ld_sw + p * 2048, qvh + tn + (size_t)p * 16 * 3072);
                CP_ASYNC16(sVl + ld_sw + p * 2048, qvl + tn + (size_t)p * 16 * 3072);
            }
            CP_COMMIT();
        }
    }

    // ---- normalize + split-bf16 writeout ----
    const size_t orow0 = (size_t)(b * SS + jq * 64 + 16 * w + g);
#pragma unroll
    for (int e = 0; e < 2; e++) {
        const float inv = 1.0f / lsum[e];
        const size_t rbase = (orow0 + 8 * e) * (size_t)DD + h * 64 + tig * 2;
#pragma unroll
        for (int ni = 0; ni < 8; ni++) {
            uint32_t H, L;
            split2(accO[ni][2*e] * inv, accO[ni][2*e+1] * inv, H, L);
            *(uint32_t*)(oh + rbase + ni * 8) = H;
            *(uint32_t*)(ol + rbase + ni * 8) = L;
        }
    }
}

// ---------------------------------------------------------------------------
// LayerNorm over D=1024, one block (256 threads) per row.
// Writes fp32 out + split bf16 (hi/lo).
// ---------------------------------------------------------------------------
__global__ __launch_bounds__(256)
void ln_kernel(const float* __restrict__ in, const float* __restrict__ w,
               const float* __restrict__ b, float* __restrict__ out,
               __nv_bfloat16* __restrict__ oh, __nv_bfloat16* __restrict__ ol)
{
    __shared__ float s_sum[8], s_sq[8], s_bc[2];
    const int row = blockIdx.x, tid = threadIdx.x;
    float4 v = ((const float4*)(in + (size_t)row * 1024))[tid];
    float s = v.x + v.y + v.z + v.w;
    float q = v.x * v.x + v.y * v.y + v.z * v.z + v.w * v.w;
#pragma unroll
    for (int o = 16; o; o >>= 1) {
        s += __shfl_xor_sync(0xffffffffu, s, o);
        q += __shfl_xor_sync(0xffffffffu, q, o);
    }
    if ((tid & 31) == 0) { s_sum[tid >> 5] = s; s_sq[tid >> 5] = q; }
    __syncthreads();
    if (tid == 0) {
        float ts = 0.f, tq = 0.f;
#pragma unroll
        for (int i = 0; i < 8; i++) { ts += s_sum[i]; tq += s_sq[i]; }
        float mu  = ts * (1.f / 1024.f);
        float var = tq * (1.f / 1024.f) - mu * mu;
        s_bc[0] = mu;
        s_bc[1] = rsqrtf(var + 1e-5f);
    }
    __syncthreads();
    float mu = s_bc[0], rs = s_bc[1];
    float4 wv = ((const float4*)w)[tid];
    float4 bv = ((const float4*)b)[tid];
    float4 ov;
    ov.x = (v.x - mu) * rs * wv.x + bv.x;
    ov.y = (v.y - mu) * rs * wv.y + bv.y;
    ov.z = (v.z - mu) * rs * wv.z + bv.z;
    ov.w = (v.w - mu) * rs * wv.w + bv.w;
    ((float4*)(out + (size_t)row * 1024))[tid] = ov;
    uint2 H, L;
    split2(ov.x, ov.y, H.x, L.x);
    split2(ov.z, ov.w, H.y, L.y);
    ((uint2*)(oh + (size_t)row * 1024))[tid] = H;
    ((uint2*)(ol + (size_t)row * 1024))[tid] = L;
}

// initial copy: x -> working fp32 buffer + split bf16
__global__ __launch_bounds__(256)
void init_kernel(const float4* __restrict__ s, float4* __restrict__ d,
                 uint2* __restrict__ hi, uint2* __restrict__ lo)
{
    int i = blockIdx.x * 256 + threadIdx.x;
    float4 v = s[i];
    d[i] = v;
    uint2 H, L;
    split2(v.x, v.y, H.x, L.x);
    split2(v.z, v.w, H.y, L.y);
    hi[i] = H;
    lo[i] = L;
}

// ---------------------------------------------------------------------------
// Host orchestration (graph-capturable: kernel launches only)
// ---------------------------------------------------------------------------
extern "C" void kernel_launch(void* const* d_in, const int* in_sizes, int n_in,
                              void* d_out, int out_size)
{
    (void)in_sizes; (void)n_in; (void)out_size;
    const float* x_in = (const float*)d_in[0];
    const float* ipw  = (const float*)d_in[1];   // [L,3072,1024]
    const float* ipb  = (const float*)d_in[2];   // [L,3072]
    const float* ow   = (const float*)d_in[3];   // [L,1024,1024]
    const float* ob   = (const float*)d_in[4];   // [L,1024]
    const float* n1w  = (const float*)d_in[5];
    const float* n1b  = (const float*)d_in[6];
    const float* f1w  = (const float*)d_in[7];   // [L,4096,1024]
    const float* f1b  = (const float*)d_in[8];   // [L,4096]
    const float* f2w  = (const float*)d_in[9];   // [L,1024,4096]
    const float* f2b  = (const float*)d_in[10];  // [L,1024]
    const float* n2w  = (const float*)d_in[11];
    const float* n2b  = (const float*)d_in[12];
    float* out = (float*)d_out;

    float *px, *ptmp;
    __nv_bfloat16 *pqh, *pql, *pxh, *pxl, *poh, *pol, *pah, *pal, *pwh, *pwl;
    cudaGetSymbolAddress((void**)&px,   g_x);
    cudaGetSymbolAddress((void**)&ptmp, g_tmp);
    cudaGetSymbolAddress((void**)&pqh,  g_qkvh);
    cudaGetSymbolAddress((void**)&pql,  g_qkvl);
    cudaGetSymbolAddress((void**)&pxh,  g_xh);
    cudaGetSymbolAddress((void**)&pxl,  g_xl);
    cudaGetSymbolAddress((void**)&poh,  g_oh);
    cudaGetSymbolAddress((void**)&pol,  g_ol);
    cudaGetSymbolAddress((void**)&pah,  g_ah);
    cudaGetSymbolAddress((void**)&pal,  g_al);
    cudaGetSymbolAddress((void**)&pwh,  g_wh);
    cudaGetSymbolAddress((void**)&pwl,  g_wl);

    cudaFuncSetAttribute((const void*)attn_tc,
                         cudaFuncAttributeMaxDynamicSharedMemorySize, ATTN_SMEM);
    cudaFuncSetAttribute((const void*)gemm_tc<EPI_BIAS>,
                         cudaFuncAttributeMaxDynamicSharedMemorySize, GEMM_SMEM);
    cudaFuncSetAttribute((const void*)gemm_tc<EPI_RELU>,
                         cudaFuncAttributeMaxDynamicSharedMemorySize, GEMM_SMEM);
    cudaFuncSetAttribute((const void*)gemm_tc<EPI_RES>,
                         cudaFuncAttributeMaxDynamicSharedMemorySize, GEMM_SMEM);
    cudaFuncSetAttribute((const void*)gemm_tc<EPI_QKV>,
                         cudaFuncAttributeMaxDynamicSharedMemorySize, GEMM_SMEM);

#define SPLIT(src, hi, lo, nelem) \
    split_kernel<<<((nelem)/4 + 255)/256, 256>>>((const float4*)(src), (uint2*)(hi), (uint2*)(lo), (nelem)/4)

    // x -> working buffer + initial split
    init_kernel<<<4096, 256>>>((const float4*)x_in, (float4*)px, (uint2*)pxh, (uint2*)pxl);

    for (int l = 0; l < NLAYERS; l++) {
        const float* Wqkv = ipw + (size_t)l * 3 * DD * DD;
        const float* Bqkv = ipb + (size_t)l * 3 * DD;
        const float* Wout = ow  + (size_t)l * DD * DD;
        const float* Bout = ob  + (size_t)l * DD;
        const float* W1   = f1w + (size_t)l * DFF * DD;
        const float* B1   = f1b + (size_t)l * DFF;
        const float* W2   = f2w + (size_t)l * DD * DFF;
        const float* B2   = f2b + (size_t)l * DD;

        // qkv = x @ Wqkv^T + b  -> split bf16 directly (Q pre-scaled by 0.125)
        SPLIT(Wqkv, pwh, pwl, 3 * DD * DD);
        gemm_tc<EPI_QKV><<<dim3(24, 32), 512, GEMM_SMEM>>>(
            pxh, pxl, pwh, pwl, Bqkv, nullptr, nullptr, pqh, pql, DD, 3 * DD);

        // tensor-core block-causal attention -> split o
        attn_tc<<<dim3(SS / 64, BB * HH), 128, ATTN_SMEM>>>(pqh, pql, poh, pol);

        // tmp = x + o @ Wout^T + b
        SPLIT(Wout, pwh, pwl, DD * DD);
        gemm_tc<EPI_RES><<<dim3(8, 32), 512, GEMM_SMEM>>>(
            poh, pol, pwh, pwl, Bout, px, ptmp, nullptr, nullptr, DD, DD);
        // x = LN1(tmp) (+ split)
        ln_kernel<<<MM, 256>>>(ptmp, n1w + (size_t)l * DD, n1b + (size_t)l * DD,
                               px, pxh, pxl);

        // h = relu(x @ W1^T + b1) -> split h directly
        SPLIT(W1, pwh, pwl, DFF * DD);
        gemm_tc<EPI_RELU><<<dim3(32, 32), 512, GEMM_SMEM>>>(
            pxh, pxl, pwh, pwl, B1, nullptr, nullptr, pah, pal, DD, DFF);

        // tmp = x + h @ W2^T + b2
        SPLIT(W2, pwh, pwl, DD * DFF);
        gemm_tc<EPI_RES><<<dim3(8, 32), 512, GEMM_SMEM>>>(
            pah, pal, pwh, pwl, B2, px, ptmp, nullptr, nullptr, DFF, DD);
        // x = LN2(tmp) (last layer writes final output)
        ln_kernel<<<MM, 256>>>(ptmp, n2w + (size_t)l * DD, n2b + (size_t)l * DD,
                               (l == NLAYERS - 1) ? out : px, pxh, pxl);
    }
#undef SPLIT
}